// round 8
// baseline (speedup 1.0000x reference)
#include <cuda_runtime.h>
#include <cuda_bf16.h>
#include <cstdint>

#define B_DIM 4096
#define D_DIM 1024
#define H1_DIM 128
#define H2_DIM 64
#define O_DIM 2

// Scratch (no cudaMalloc allowed)
__device__ float g_h1[B_DIM * H1_DIM];
__device__ float g_pr0[B_DIM * H1_DIM];
__device__ float g_pr1[B_DIM * H1_DIM];

// ---------------------------------------------------------------------------
// Packed fp32x2 helpers (Blackwell FFMA2 — only reachable via PTX)
// ---------------------------------------------------------------------------
__device__ __forceinline__ unsigned long long pk2(float x, float y) {
    unsigned long long r;
    asm("mov.b64 %0, {%1, %2};" : "=l"(r) : "f"(x), "f"(y));
    return r;
}
__device__ __forceinline__ void ffma2(unsigned long long& d,
                                      unsigned long long a,
                                      unsigned long long b) {
    asm("fma.rn.f32x2 %0, %1, %2, %0;" : "+l"(d) : "l"(a), "l"(b));
}
__device__ __forceinline__ float2 upk2(unsigned long long v) {
    float2 f;
    asm("mov.b64 {%0, %1}, %2;" : "=f"(f.x), "=f"(f.y) : "l"(v));
    return f;
}

// ---------------------------------------------------------------------------
// Pipelined SGEMM with FFMA2: C[M,N] = act(A[M,K] @ B[N,K]^T + bias)
// BM in {16,32}, BN=64, BK=32, 128 threads. grid = (M/BM, N/64).
// Rows per thread RPT = BM/16 (16 row-groups of threads).
// ---------------------------------------------------------------------------
template <int BM, bool RELU>
__global__ __launch_bounds__(128) void gemm_f2_kernel(
    const float* __restrict__ A, const float* __restrict__ Bm,
    const float* __restrict__ bias, float* __restrict__ C,
    int M, int N, int K)
{
    constexpr int BK = 32;
    constexpr int RPT = BM / 16;
    static_assert(BM == 16 || BM == 32, "BM must be 16 or 32");

    __shared__ float As[BM][BK + 1];
    __shared__ float Bs[BK][68];

    const int tid = threadIdx.x;
    const int tx = tid & 7;        // 8 col groups
    const int ty = tid >> 3;       // 16 row groups -> rows ty*RPT .. +RPT-1
    const int row0 = blockIdx.x * BM;
    const int col0 = blockIdx.y * 64;
    const float* Bp = Bm + (size_t)col0 * K;

    const int l_kq = tid & 7;
    const int l_r  = tid >> 3;

    unsigned long long acc[RPT][4];
#pragma unroll
    for (int i = 0; i < RPT; i++)
#pragma unroll
        for (int j = 0; j < 4; j++) acc[i][j] = 0ull;

    const int NB = K / BK;
    float4 pa[RPT], pb[4];

#pragma unroll
    for (int it = 0; it < RPT; it++)
        pa[it] = *(const float4*)&A[(size_t)(row0 + l_r + it * 16) * K + l_kq * 4];
#pragma unroll
    for (int it = 0; it < 4; it++)
        pb[it] = *(const float4*)&Bp[(size_t)(l_r + it * 16) * K + l_kq * 4];

#pragma unroll
    for (int it = 0; it < RPT; it++) {
        int r = l_r + it * 16;
        As[r][l_kq * 4 + 0] = pa[it].x; As[r][l_kq * 4 + 1] = pa[it].y;
        As[r][l_kq * 4 + 2] = pa[it].z; As[r][l_kq * 4 + 3] = pa[it].w;
    }
#pragma unroll
    for (int it = 0; it < 4; it++) {
        int f = l_r + it * 16;
        Bs[l_kq * 4 + 0][f] = pb[it].x; Bs[l_kq * 4 + 1][f] = pb[it].y;
        Bs[l_kq * 4 + 2][f] = pb[it].z; Bs[l_kq * 4 + 3][f] = pb[it].w;
    }
    __syncthreads();

    const int tyR = ty * RPT;
    for (int kb = 0; kb < NB; kb++) {
        const bool more = (kb + 1 < NB);
        if (more) {
            const int k0 = (kb + 1) * BK;
#pragma unroll
            for (int it = 0; it < RPT; it++)
                pa[it] = *(const float4*)&A[(size_t)(row0 + l_r + it * 16) * K + k0 + l_kq * 4];
#pragma unroll
            for (int it = 0; it < 4; it++)
                pb[it] = *(const float4*)&Bp[(size_t)(l_r + it * 16) * K + k0 + l_kq * 4];
        }

#pragma unroll
        for (int kk = 0; kk < BK; kk++) {
            ulonglong2 b01 = *(const ulonglong2*)&Bs[kk][tx * 4];
            ulonglong2 b23 = *(const ulonglong2*)&Bs[kk][32 + tx * 4];
#pragma unroll
            for (int i = 0; i < RPT; i++) {
                float a = As[tyR + i][kk];
                unsigned long long ap = pk2(a, a);
                ffma2(acc[i][0], ap, b01.x); ffma2(acc[i][1], ap, b01.y);
                ffma2(acc[i][2], ap, b23.x); ffma2(acc[i][3], ap, b23.y);
            }
        }
        __syncthreads();
        if (more) {
#pragma unroll
            for (int it = 0; it < RPT; it++) {
                int r = l_r + it * 16;
                As[r][l_kq * 4 + 0] = pa[it].x; As[r][l_kq * 4 + 1] = pa[it].y;
                As[r][l_kq * 4 + 2] = pa[it].z; As[r][l_kq * 4 + 3] = pa[it].w;
            }
#pragma unroll
            for (int it = 0; it < 4; it++) {
                int f = l_r + it * 16;
                Bs[l_kq * 4 + 0][f] = pb[it].x; Bs[l_kq * 4 + 1][f] = pb[it].y;
                Bs[l_kq * 4 + 2][f] = pb[it].z; Bs[l_kq * 4 + 3][f] = pb[it].w;
            }
            __syncthreads();
        }
    }

#pragma unroll
    for (int i = 0; i < RPT; i++) {
        const int r = row0 + tyR + i;
#pragma unroll
        for (int half = 0; half < 2; half++) {
            const int c = half * 32 + tx * 4;
            float2 p0 = upk2(acc[i][half * 2 + 0]);
            float2 p1 = upk2(acc[i][half * 2 + 1]);
            float4 v;
            v.x = p0.x + bias[col0 + c + 0];
            v.y = p0.y + bias[col0 + c + 1];
            v.z = p1.x + bias[col0 + c + 2];
            v.w = p1.y + bias[col0 + c + 3];
            if (RELU) {
                v.x = fmaxf(v.x, 0.0f); v.y = fmaxf(v.y, 0.0f);
                v.z = fmaxf(v.z, 0.0f); v.w = fmaxf(v.w, 0.0f);
            }
            *(float4*)&C[(size_t)r * N + col0 + c] = v;
        }
    }
}

// ---------------------------------------------------------------------------
// Per-feature 6-NN batch averaging. One CTA per feature (128 CTAs, 1024 thr).
// Sort only the 32-bit value bits (post-ReLU values >= 0 so IEEE bits are
// unsigned-order-monotonic); recover each element's rank by binary search.
// For equal-value runs the frontier walk's 6-value multiset is independent of
// position within the run, so lower_bound rank is exact.
// ---------------------------------------------------------------------------
__global__ __launch_bounds__(1024) void knn_mean_kernel(
    const float* __restrict__ h1, float* __restrict__ out)
{
    __shared__ unsigned int sv[B_DIM];  // 16 KB

    const int f = blockIdx.x;
    const int tid = threadIdx.x;

    unsigned int myv[4];
#pragma unroll
    for (int q = 0; q < 4; q++) {
        int b = tid + q * 1024;
        unsigned int bits = __float_as_uint(h1[(size_t)b * H1_DIM + f]);
        myv[q] = bits;
        sv[b] = bits;
    }
    __syncthreads();

    // Bitonic sort ascending (u32), exact pair indexing: 2 CE per thread/phase
    for (int k = 2; k <= B_DIM; k <<= 1) {
        for (int j = k >> 1; j > 0; j >>= 1) {
#pragma unroll 2
            for (int p = tid; p < B_DIM / 2; p += 1024) {
                int i = ((p & ~(j - 1)) << 1) | (p & (j - 1));
                int ixj = i | j;
                unsigned int a = sv[i];
                unsigned int b = sv[ixj];
                bool up = (i & k) == 0;
                if (up ? (a > b) : (a < b)) { sv[i] = b; sv[ixj] = a; }
            }
            __syncthreads();
        }
    }

    const float BIG = __int_as_float(0x7f000000);

#pragma unroll
    for (int q = 0; q < 4; q++) {
        int b = tid + q * 1024;
        unsigned int vb = myv[q];
        // lower_bound over 4096 sorted keys: exactly 12 halvings
        int lo = 0, hi = B_DIM;
#pragma unroll
        for (int s = 0; s < 12; s++) {
            int mid = (lo + hi) >> 1;
            if (sv[mid] < vb) lo = mid + 1; else hi = mid;
        }
        int p = lo;  // sv[p] == vb
        float v = __uint_as_float(vb);
        float sum = v;
        int l = p - 1, r = p + 1;
#pragma unroll
        for (int s = 0; s < 5; s++) {
            float vl = (l >= 0)    ? __uint_as_float(sv[l]) : 0.0f;
            float vr = (r < B_DIM) ? __uint_as_float(sv[r]) : 0.0f;
            float dl = (l >= 0)    ? (v - vl) : BIG;
            float dr = (r < B_DIM) ? (vr - v) : BIG;
            if (dl <= dr) { sum += vl; l--; }
            else          { sum += vr; r++; }
        }
        out[(size_t)b * H1_DIM + f] = sum * (1.0f / 6.0f);
    }
}

// ---------------------------------------------------------------------------
// Fused tail: h2 = relu(pr1 @ W2^T + b2); out = h2 @ Wo^T + bo
// Pipelined gemm structure (BM=32, N=64, K=128), 128 CTAs x 128 threads.
// Projection to 2 outputs fused via smem h2 tile.
// ---------------------------------------------------------------------------
__global__ __launch_bounds__(128) void tail_fused_kernel(
    const float* __restrict__ A,    // pr1 [4096,128]
    const float* __restrict__ W2,   // [64,128]
    const float* __restrict__ b2,   // [64]
    const float* __restrict__ Wo,   // [2,64]
    const float* __restrict__ bo,   // [2]
    float* __restrict__ out)        // [4096,2]
{
    constexpr int BM = 32, BK = 32, K = H1_DIM, NB = K / BK;
    __shared__ float As[BM][BK + 1];
    __shared__ float Bs[BK][68];
    __shared__ float h2s[BM][H2_DIM + 1];   // 32 x 65
    __shared__ float wos[O_DIM * H2_DIM];   // 128
    __shared__ float b2s[H2_DIM];
    __shared__ float bos[O_DIM];

    const int tid = threadIdx.x;
    const int tx = tid & 7;
    const int ty = tid >> 3;
    const int row0 = blockIdx.x * BM;

    const int l_kq = tid & 7;
    const int l_r  = tid >> 3;

    wos[tid] = Wo[tid];                 // 128 threads, 128 elems
    if (tid < H2_DIM) b2s[tid] = b2[tid];
    if (tid < O_DIM)  bos[tid] = bo[tid];

    unsigned long long acc[2][4];
#pragma unroll
    for (int i = 0; i < 2; i++)
#pragma unroll
        for (int j = 0; j < 4; j++) acc[i][j] = 0ull;

    float4 pa[2], pb[4];
#pragma unroll
    for (int it = 0; it < 2; it++)
        pa[it] = *(const float4*)&A[(size_t)(row0 + l_r + it * 16) * K + l_kq * 4];
#pragma unroll
    for (int it = 0; it < 4; it++)
        pb[it] = *(const float4*)&W2[(size_t)(l_r + it * 16) * K + l_kq * 4];

#pragma unroll
    for (int it = 0; it < 2; it++) {
        int r = l_r + it * 16;
        As[r][l_kq * 4 + 0] = pa[it].x; As[r][l_kq * 4 + 1] = pa[it].y;
        As[r][l_kq * 4 + 2] = pa[it].z; As[r][l_kq * 4 + 3] = pa[it].w;
    }
#pragma unroll
    for (int it = 0; it < 4; it++) {
        int c = l_r + it * 16;
        Bs[l_kq * 4 + 0][c] = pb[it].x; Bs[l_kq * 4 + 1][c] = pb[it].y;
        Bs[l_kq * 4 + 2][c] = pb[it].z; Bs[l_kq * 4 + 3][c] = pb[it].w;
    }
    __syncthreads();

    const int ty2 = ty * 2;
#pragma unroll
    for (int kb = 0; kb < NB; kb++) {
        const bool more = (kb + 1 < NB);
        if (more) {
            const int k0 = (kb + 1) * BK;
#pragma unroll
            for (int it = 0; it < 2; it++)
                pa[it] = *(const float4*)&A[(size_t)(row0 + l_r + it * 16) * K + k0 + l_kq * 4];
#pragma unroll
            for (int it = 0; it < 4; it++)
                pb[it] = *(const float4*)&W2[(size_t)(l_r + it * 16) * K + k0 + l_kq * 4];
        }
#pragma unroll
        for (int kk = 0; kk < BK; kk++) {
            float a0 = As[ty2][kk];
            float a1 = As[ty2 + 1][kk];
            unsigned long long ap0 = pk2(a0, a0);
            unsigned long long ap1 = pk2(a1, a1);
            ulonglong2 b01 = *(const ulonglong2*)&Bs[kk][tx * 4];
            ulonglong2 b23 = *(const ulonglong2*)&Bs[kk][32 + tx * 4];
            ffma2(acc[0][0], ap0, b01.x); ffma2(acc[0][1], ap0, b01.y);
            ffma2(acc[0][2], ap0, b23.x); ffma2(acc[0][3], ap0, b23.y);
            ffma2(acc[1][0], ap1, b01.x); ffma2(acc[1][1], ap1, b01.y);
            ffma2(acc[1][2], ap1, b23.x); ffma2(acc[1][3], ap1, b23.y);
        }
        __syncthreads();
        if (more) {
#pragma unroll
            for (int it = 0; it < 2; it++) {
                int r = l_r + it * 16;
                As[r][l_kq * 4 + 0] = pa[it].x; As[r][l_kq * 4 + 1] = pa[it].y;
                As[r][l_kq * 4 + 2] = pa[it].z; As[r][l_kq * 4 + 3] = pa[it].w;
            }
#pragma unroll
            for (int it = 0; it < 4; it++) {
                int c = l_r + it * 16;
                Bs[l_kq * 4 + 0][c] = pb[it].x; Bs[l_kq * 4 + 1][c] = pb[it].y;
                Bs[l_kq * 4 + 2][c] = pb[it].z; Bs[l_kq * 4 + 3][c] = pb[it].w;
            }
            __syncthreads();
        }
    }

    // h2 tile -> smem with bias + ReLU
#pragma unroll
    for (int i = 0; i < 2; i++) {
        const int r = ty2 + i;
#pragma unroll
        for (int half = 0; half < 2; half++) {
            const int c = half * 32 + tx * 4;
            float2 p0 = upk2(acc[i][half * 2 + 0]);
            float2 p1 = upk2(acc[i][half * 2 + 1]);
            h2s[r][c + 0] = fmaxf(p0.x + b2s[c + 0], 0.0f);
            h2s[r][c + 1] = fmaxf(p0.y + b2s[c + 1], 0.0f);
            h2s[r][c + 2] = fmaxf(p1.x + b2s[c + 2], 0.0f);
            h2s[r][c + 3] = fmaxf(p1.y + b2s[c + 3], 0.0f);
        }
    }
    __syncthreads();

    // Projection: 64 work items (32 rows x 2 outs)
    if (tid < BM * O_DIM) {
        int r = tid >> 1, o = tid & 1;
        float s = 0.0f;
        const float* w = &wos[o * H2_DIM];
#pragma unroll
        for (int k = 0; k < H2_DIM; k++)
            s = fmaf(h2s[r][k], w[k], s);
        out[(size_t)(row0 + r) * O_DIM + o] = s + bos[o];
    }
}

// ---------------------------------------------------------------------------
extern "C" void kernel_launch(void* const* d_in, const int* in_sizes, int n_in,
                              void* d_out, int out_size)
{
    const float* x   = (const float*)d_in[0];
    const float* W1  = (const float*)d_in[1];
    const float* b1  = (const float*)d_in[2];
    const float* Wpr = (const float*)d_in[3];
    const float* bpr = (const float*)d_in[4];
    const float* W2  = (const float*)d_in[5];
    const float* b2  = (const float*)d_in[6];
    const float* Wo  = (const float*)d_in[7];
    const float* bo  = (const float*)d_in[8];
    float* out = (float*)d_out;

    float *h1, *pr0, *pr1;
    cudaGetSymbolAddress((void**)&h1,  g_h1);
    cudaGetSymbolAddress((void**)&pr0, g_pr0);
    cudaGetSymbolAddress((void**)&pr1, g_pr1);

    // 1) h1 = relu(x @ W1^T + b1)        [4096,128], K=1024, 512 CTAs
    gemm_f2_kernel<16, true><<<dim3(B_DIM / 16, H1_DIM / 64), 128>>>(
        x, W1, b1, h1, B_DIM, H1_DIM, D_DIM);
    // 2) pr0 = per-feature 6-NN mean
    knn_mean_kernel<<<H1_DIM, 1024>>>(h1, pr0);
    // 3) pr1 = relu(pr0 @ Wpr^T + bpr)   [4096,128], K=128, 512 CTAs
    gemm_f2_kernel<16, true><<<dim3(B_DIM / 16, H1_DIM / 64), 128>>>(
        pr0, Wpr, bpr, pr1, B_DIM, H1_DIM, H1_DIM);
    // 4) fused h2 + output projection
    tail_fused_kernel<<<B_DIM / 32, 128>>>(pr1, W2, b2, Wo, bo, out);
}

// round 10
// speedup vs baseline: 1.5690x; 1.5690x over previous
#include <cuda_runtime.h>
#include <cuda_bf16.h>
#include <cstdint>

#define B_DIM 4096
#define D_DIM 1024
#define H1_DIM 128
#define H2_DIM 64
#define O_DIM 2

// Scratch (no cudaMalloc allowed)
__device__ float g_h1[B_DIM * H1_DIM];
__device__ float g_pr0[B_DIM * H1_DIM];
__device__ float g_pr1[B_DIM * H1_DIM];

// ---------------------------------------------------------------------------
// Packed fp32x2 helpers (Blackwell FFMA2 — only reachable via PTX)
// ---------------------------------------------------------------------------
__device__ __forceinline__ unsigned long long pk2(float x, float y) {
    unsigned long long r;
    asm("mov.b64 %0, {%1, %2};" : "=l"(r) : "f"(x), "f"(y));
    return r;
}
__device__ __forceinline__ void ffma2(unsigned long long& d,
                                      unsigned long long a,
                                      unsigned long long b) {
    asm("fma.rn.f32x2 %0, %1, %2, %0;" : "+l"(d) : "l"(a), "l"(b));
}
__device__ __forceinline__ float2 upk2(unsigned long long v) {
    float2 f;
    asm("mov.b64 {%0, %1}, %2;" : "=f"(f.x), "=f"(f.y) : "l"(v));
    return f;
}

// ---------------------------------------------------------------------------
// Pipelined SGEMM with FFMA2: C[M,N] = act(A[M,K] @ B[N,K]^T + bias)
// BM=32 (measured-best shape), BN=64, BK=32, 128 threads. grid=(M/32, N/64).
// ---------------------------------------------------------------------------
template <bool RELU>
__global__ __launch_bounds__(128) void gemm_f2_kernel(
    const float* __restrict__ A, const float* __restrict__ Bm,
    const float* __restrict__ bias, float* __restrict__ C,
    int M, int N, int K)
{
    constexpr int BM = 32, BK = 32;
    __shared__ float As[BM][BK + 1];
    __shared__ float Bs[BK][68];

    const int tid = threadIdx.x;
    const int tx = tid & 7;
    const int ty = tid >> 3;
    const int row0 = blockIdx.x * BM;
    const int col0 = blockIdx.y * 64;
    const float* Bp = Bm + (size_t)col0 * K;

    const int l_kq = tid & 7;
    const int l_r  = tid >> 3;

    unsigned long long acc[2][4];
#pragma unroll
    for (int i = 0; i < 2; i++)
#pragma unroll
        for (int j = 0; j < 4; j++) acc[i][j] = 0ull;

    const int NB = K / BK;
    float4 pa[2], pb[4];

#pragma unroll
    for (int it = 0; it < 2; it++)
        pa[it] = *(const float4*)&A[(size_t)(row0 + l_r + it * 16) * K + l_kq * 4];
#pragma unroll
    for (int it = 0; it < 4; it++)
        pb[it] = *(const float4*)&Bp[(size_t)(l_r + it * 16) * K + l_kq * 4];

#pragma unroll
    for (int it = 0; it < 2; it++) {
        int r = l_r + it * 16;
        As[r][l_kq * 4 + 0] = pa[it].x; As[r][l_kq * 4 + 1] = pa[it].y;
        As[r][l_kq * 4 + 2] = pa[it].z; As[r][l_kq * 4 + 3] = pa[it].w;
    }
#pragma unroll
    for (int it = 0; it < 4; it++) {
        int f = l_r + it * 16;
        Bs[l_kq * 4 + 0][f] = pb[it].x; Bs[l_kq * 4 + 1][f] = pb[it].y;
        Bs[l_kq * 4 + 2][f] = pb[it].z; Bs[l_kq * 4 + 3][f] = pb[it].w;
    }
    __syncthreads();

    const int ty2 = ty * 2;
    for (int kb = 0; kb < NB; kb++) {
        const bool more = (kb + 1 < NB);
        if (more) {
            const int k0 = (kb + 1) * BK;
#pragma unroll
            for (int it = 0; it < 2; it++)
                pa[it] = *(const float4*)&A[(size_t)(row0 + l_r + it * 16) * K + k0 + l_kq * 4];
#pragma unroll
            for (int it = 0; it < 4; it++)
                pb[it] = *(const float4*)&Bp[(size_t)(l_r + it * 16) * K + k0 + l_kq * 4];
        }

#pragma unroll
        for (int kk = 0; kk < BK; kk++) {
            float a0 = As[ty2][kk];
            float a1 = As[ty2 + 1][kk];
            unsigned long long ap0 = pk2(a0, a0);
            unsigned long long ap1 = pk2(a1, a1);
            ulonglong2 b01 = *(const ulonglong2*)&Bs[kk][tx * 4];
            ulonglong2 b23 = *(const ulonglong2*)&Bs[kk][32 + tx * 4];
            ffma2(acc[0][0], ap0, b01.x); ffma2(acc[0][1], ap0, b01.y);
            ffma2(acc[0][2], ap0, b23.x); ffma2(acc[0][3], ap0, b23.y);
            ffma2(acc[1][0], ap1, b01.x); ffma2(acc[1][1], ap1, b01.y);
            ffma2(acc[1][2], ap1, b23.x); ffma2(acc[1][3], ap1, b23.y);
        }
        __syncthreads();
        if (more) {
#pragma unroll
            for (int it = 0; it < 2; it++) {
                int r = l_r + it * 16;
                As[r][l_kq * 4 + 0] = pa[it].x; As[r][l_kq * 4 + 1] = pa[it].y;
                As[r][l_kq * 4 + 2] = pa[it].z; As[r][l_kq * 4 + 3] = pa[it].w;
            }
#pragma unroll
            for (int it = 0; it < 4; it++) {
                int f = l_r + it * 16;
                Bs[l_kq * 4 + 0][f] = pb[it].x; Bs[l_kq * 4 + 1][f] = pb[it].y;
                Bs[l_kq * 4 + 2][f] = pb[it].z; Bs[l_kq * 4 + 3][f] = pb[it].w;
            }
            __syncthreads();
        }
    }

#pragma unroll
    for (int i = 0; i < 2; i++) {
        const int r = row0 + ty2 + i;
#pragma unroll
        for (int half = 0; half < 2; half++) {
            const int c = half * 32 + tx * 4;
            float2 p0 = upk2(acc[i][half * 2 + 0]);
            float2 p1 = upk2(acc[i][half * 2 + 1]);
            float4 v;
            v.x = p0.x + bias[col0 + c + 0];
            v.y = p0.y + bias[col0 + c + 1];
            v.z = p1.x + bias[col0 + c + 2];
            v.w = p1.y + bias[col0 + c + 3];
            if (RELU) {
                v.x = fmaxf(v.x, 0.0f); v.y = fmaxf(v.y, 0.0f);
                v.z = fmaxf(v.z, 0.0f); v.w = fmaxf(v.w, 0.0f);
            }
            *(float4*)&C[(size_t)r * N + col0 + c] = v;
        }
    }
}

// ---------------------------------------------------------------------------
// Per-feature 6-NN batch averaging. One CTA per feature (128 CTAs, 1024 thr).
// Hybrid bitonic sort of the 32-bit value bits (post-ReLU => unsigned-order-
// monotonic): thread t owns elements [4t..4t+3] in registers. Phases j in
// {1,2} are in-thread, j in {4..64} are warp shuffles (partner lane t^(j/4)),
// only j>=128 goes through shared memory (15 phases, ~20 barriers vs 78).
// Identical compare network to the classic formulation. Rank recovered by
// binary search; frontier walk handles the 6-NN mean (duplicate-run multiset
// is position-independent, so lower_bound rank is exact).
// ---------------------------------------------------------------------------
__device__ __forceinline__ void ce_u32(unsigned int& a, unsigned int& b, bool up) {
    unsigned int mn = min(a, b), mx = max(a, b);
    a = up ? mn : mx;
    b = up ? mx : mn;
}

__global__ __launch_bounds__(1024) void knn_mean_kernel(
    const float* __restrict__ h1, float* __restrict__ out)
{
    __shared__ unsigned int sv[B_DIM];  // 16 KB

    const int f = blockIdx.x;
    const int t = threadIdx.x;
    const int lane = t & 31;
    const unsigned int i0 = 4u * (unsigned)t;

    unsigned int v[4], myv[4];
#pragma unroll
    for (int e = 0; e < 4; e++) {
        v[e] = __float_as_uint(h1[(size_t)(i0 + e) * H1_DIM + f]);
        myv[e] = v[e];
    }

    // k = 2: pair (0,1) ascending, pair (2,3) descending
    {
        if (v[0] > v[1]) { unsigned int tm = v[0]; v[0] = v[1]; v[1] = tm; }
        if (v[2] < v[3]) { unsigned int tm = v[2]; v[2] = v[3]; v[3] = tm; }
    }
    // k = 4: dir = (t&1)==0; phases j=2 then j=1 (both in-thread)
    {
        bool up = (t & 1) == 0;
        ce_u32(v[0], v[2], up); ce_u32(v[1], v[3], up);
        ce_u32(v[0], v[1], up); ce_u32(v[2], v[3], up);
    }

    for (unsigned int k = 8; k <= B_DIM; k <<= 1) {
        const bool up = ((i0 & k) == 0);
        unsigned int j = k >> 1;

        // --- smem phases: j >= 128 (cross-warp partners) ---
        if (j >= 128) {
            *(uint4*)&sv[i0] = make_uint4(v[0], v[1], v[2], v[3]);
            __syncthreads();
            for (; j >= 128; j >>= 1) {
#pragma unroll 2
                for (int p = t; p < B_DIM / 2; p += 1024) {
                    int i = ((p & ~(int)(j - 1)) << 1) | (p & (int)(j - 1));
                    int ixj = i | (int)j;
                    unsigned int a = sv[i];
                    unsigned int b = sv[ixj];
                    bool u2 = ((i & (int)k) == 0);
                    if (u2 ? (a > b) : (a < b)) { sv[i] = b; sv[ixj] = a; }
                }
                __syncthreads();
            }
            uint4 u = *(const uint4*)&sv[i0];
            v[0] = u.x; v[1] = u.y; v[2] = u.z; v[3] = u.w;
        }

        // --- shuffle phases: 64 >= j >= 4 (partner lane = lane ^ (j/4)) ---
        for (; j >= 4; j >>= 1) {
            const unsigned int d = j >> 2;
            const bool keepmin = (up == ((lane & d) == 0));
#pragma unroll
            for (int e = 0; e < 4; e++) {
                unsigned int o = __shfl_xor_sync(0xFFFFFFFFu, v[e], d);
                unsigned int mn = min(v[e], o), mx = max(v[e], o);
                v[e] = keepmin ? mn : mx;
            }
        }

        // --- in-thread phases: j = 2 then j = 1 ---
        ce_u32(v[0], v[2], up); ce_u32(v[1], v[3], up);
        ce_u32(v[0], v[1], up); ce_u32(v[2], v[3], up);
    }

    // Publish sorted array
    *(uint4*)&sv[i0] = make_uint4(v[0], v[1], v[2], v[3]);
    __syncthreads();

    const float BIG = __int_as_float(0x7f000000);

#pragma unroll
    for (int e = 0; e < 4; e++) {
        const int b = (int)i0 + e;
        const unsigned int vb = myv[e];
        // lower_bound over 4096 sorted keys: exactly 12 halvings
        int lo = 0, hi = B_DIM;
#pragma unroll
        for (int s = 0; s < 12; s++) {
            int mid = (lo + hi) >> 1;
            if (sv[mid] < vb) lo = mid + 1; else hi = mid;
        }
        int p = lo;  // sv[p] == vb
        float val = __uint_as_float(vb);
        float sum = val;
        int l = p - 1, r = p + 1;
#pragma unroll
        for (int s = 0; s < 5; s++) {
            float vl = (l >= 0)     ? __uint_as_float(sv[l]) : 0.0f;
            float vr = (r < B_DIM)  ? __uint_as_float(sv[r]) : 0.0f;
            float dl = (l >= 0)     ? (val - vl) : BIG;
            float dr = (r < B_DIM)  ? (vr - val) : BIG;
            if (dl <= dr) { sum += vl; l--; }
            else          { sum += vr; r++; }
        }
        out[(size_t)b * H1_DIM + f] = sum * (1.0f / 6.0f);
    }
}

// ---------------------------------------------------------------------------
// Fused tail: h2 = relu(pr1 @ W2^T + b2); out = h2 @ Wo^T + bo
// Pipelined gemm (BM=32, N=64, K=128), 128 CTAs x 128 threads. Measured 11.3us.
// ---------------------------------------------------------------------------
__global__ __launch_bounds__(128) void tail_fused_kernel(
    const float* __restrict__ A,    // pr1 [4096,128]
    const float* __restrict__ W2,   // [64,128]
    const float* __restrict__ b2,   // [64]
    const float* __restrict__ Wo,   // [2,64]
    const float* __restrict__ bo,   // [2]
    float* __restrict__ out)        // [4096,2]
{
    constexpr int BM = 32, BK = 32, K = H1_DIM, NB = K / BK;
    __shared__ float As[BM][BK + 1];
    __shared__ float Bs[BK][68];
    __shared__ float h2s[BM][H2_DIM + 1];
    __shared__ float wos[O_DIM * H2_DIM];
    __shared__ float b2s[H2_DIM];
    __shared__ float bos[O_DIM];

    const int tid = threadIdx.x;
    const int tx = tid & 7;
    const int ty = tid >> 3;
    const int row0 = blockIdx.x * BM;

    const int l_kq = tid & 7;
    const int l_r  = tid >> 3;

    wos[tid] = Wo[tid];
    if (tid < H2_DIM) b2s[tid] = b2[tid];
    if (tid < O_DIM)  bos[tid] = bo[tid];

    unsigned long long acc[2][4];
#pragma unroll
    for (int i = 0; i < 2; i++)
#pragma unroll
        for (int j = 0; j < 4; j++) acc[i][j] = 0ull;

    float4 pa[2], pb[4];
#pragma unroll
    for (int it = 0; it < 2; it++)
        pa[it] = *(const float4*)&A[(size_t)(row0 + l_r + it * 16) * K + l_kq * 4];
#pragma unroll
    for (int it = 0; it < 4; it++)
        pb[it] = *(const float4*)&W2[(size_t)(l_r + it * 16) * K + l_kq * 4];

#pragma unroll
    for (int it = 0; it < 2; it++) {
        int r = l_r + it * 16;
        As[r][l_kq * 4 + 0] = pa[it].x; As[r][l_kq * 4 + 1] = pa[it].y;
        As[r][l_kq * 4 + 2] = pa[it].z; As[r][l_kq * 4 + 3] = pa[it].w;
    }
#pragma unroll
    for (int it = 0; it < 4; it++) {
        int c = l_r + it * 16;
        Bs[l_kq * 4 + 0][c] = pb[it].x; Bs[l_kq * 4 + 1][c] = pb[it].y;
        Bs[l_kq * 4 + 2][c] = pb[it].z; Bs[l_kq * 4 + 3][c] = pb[it].w;
    }
    __syncthreads();

    const int ty2 = ty * 2;
#pragma unroll
    for (int kb = 0; kb < NB; kb++) {
        const bool more = (kb + 1 < NB);
        if (more) {
            const int k0 = (kb + 1) * BK;
#pragma unroll
            for (int it = 0; it < 2; it++)
                pa[it] = *(const float4*)&A[(size_t)(row0 + l_r + it * 16) * K + k0 + l_kq * 4];
#pragma unroll
            for (int it = 0; it < 4; it++)
                pb[it] = *(const float4*)&W2[(size_t)(l_r + it * 16) * K + k0 + l_kq * 4];
        }
#pragma unroll
        for (int kk = 0; kk < BK; kk++) {
            float a0 = As[ty2][kk];
            float a1 = As[ty2 + 1][kk];
            unsigned long long ap0 = pk2(a0, a0);
            unsigned long long ap1 = pk2(a1, a1);
            ulonglong2 b01 = *(const ulonglong2*)&Bs[kk][tx * 4];
            ulonglong2 b23 = *(const ulonglong2*)&Bs[kk][32 + tx * 4];
            ffma2(acc[0][0], ap0, b01.x); ffma2(acc[0][1], ap0, b01.y);
            ffma2(acc[0][2], ap0, b23.x); ffma2(acc[0][3], ap0, b23.y);
            ffma2(acc[1][0], ap1, b01.x); ffma2(acc[1][1], ap1, b01.y);
            ffma2(acc[1][2], ap1, b23.x); ffma2(acc[1][3], ap1, b23.y);
        }
        __syncthreads();
        if (more) {
#pragma unroll
            for (int it = 0; it < 2; it++) {
                int r = l_r + it * 16;
                As[r][l_kq * 4 + 0] = pa[it].x; As[r][l_kq * 4 + 1] = pa[it].y;
                As[r][l_kq * 4 + 2] = pa[it].z; As[r][l_kq * 4 + 3] = pa[it].w;
            }
#pragma unroll
            for (int it = 0; it < 4; it++) {
                int c = l_r + it * 16;
                Bs[l_kq * 4 + 0][c] = pb[it].x; Bs[l_kq * 4 + 1][c] = pb[it].y;
                Bs[l_kq * 4 + 2][c] = pb[it].z; Bs[l_kq * 4 + 3][c] = pb[it].w;
            }
            __syncthreads();
        }
    }

    // h2 tile -> smem with bias + ReLU
#pragma unroll
    for (int i = 0; i < 2; i++) {
        const int r = ty2 + i;
#pragma unroll
        for (int half = 0; half < 2; half++) {
            const int c = half * 32 + tx * 4;
            float2 p0 = upk2(acc[i][half * 2 + 0]);
            float2 p1 = upk2(acc[i][half * 2 + 1]);
            h2s[r][c + 0] = fmaxf(p0.x + b2s[c + 0], 0.0f);
            h2s[r][c + 1] = fmaxf(p0.y + b2s[c + 1], 0.0f);
            h2s[r][c + 2] = fmaxf(p1.x + b2s[c + 2], 0.0f);
            h2s[r][c + 3] = fmaxf(p1.y + b2s[c + 3], 0.0f);
        }
    }
    __syncthreads();

    // Projection: 64 work items (32 rows x 2 outs)
    if (tid < BM * O_DIM) {
        int r = tid >> 1, o = tid & 1;
        float s = 0.0f;
        const float* w = &wos[o * H2_DIM];
#pragma unroll
        for (int k = 0; k < H2_DIM; k++)
            s = fmaf(h2s[r][k], w[k], s);
        out[(size_t)(row0 + r) * O_DIM + o] = s + bos[o];
    }
}

// ---------------------------------------------------------------------------
extern "C" void kernel_launch(void* const* d_in, const int* in_sizes, int n_in,
                              void* d_out, int out_size)
{
    const float* x   = (const float*)d_in[0];
    const float* W1  = (const float*)d_in[1];
    const float* b1  = (const float*)d_in[2];
    const float* Wpr = (const float*)d_in[3];
    const float* bpr = (const float*)d_in[4];
    const float* W2  = (const float*)d_in[5];
    const float* b2  = (const float*)d_in[6];
    const float* Wo  = (const float*)d_in[7];
    const float* bo  = (const float*)d_in[8];
    float* out = (float*)d_out;

    float *h1, *pr0, *pr1;
    cudaGetSymbolAddress((void**)&h1,  g_h1);
    cudaGetSymbolAddress((void**)&pr0, g_pr0);
    cudaGetSymbolAddress((void**)&pr1, g_pr1);

    // 1) h1 = relu(x @ W1^T + b1)        [4096,128], K=1024, 256 CTAs (BM=32)
    gemm_f2_kernel<true><<<dim3(B_DIM / 32, H1_DIM / 64), 128>>>(
        x, W1, b1, h1, B_DIM, H1_DIM, D_DIM);
    // 2) pr0 = per-feature 6-NN mean (hybrid register/shuffle/smem bitonic)
    knn_mean_kernel<<<H1_DIM, 1024>>>(h1, pr0);
    // 3) pr1 = relu(pr0 @ Wpr^T + bpr)   [4096,128], K=128, 256 CTAs (BM=32)
    gemm_f2_kernel<true><<<dim3(B_DIM / 32, H1_DIM / 64), 128>>>(
        pr0, Wpr, bpr, pr1, B_DIM, H1_DIM, H1_DIM);
    // 4) fused h2 + output projection
    tail_fused_kernel<<<B_DIM / 32, 128>>>(pr1, W2, b2, Wo, bo, out);
}

// round 11
// speedup vs baseline: 1.6183x; 1.0314x over previous
#include <cuda_runtime.h>
#include <cuda_bf16.h>
#include <cstdint>

#define B_DIM 4096
#define D_DIM 1024
#define H1_DIM 128
#define H2_DIM 64
#define O_DIM 2
#define KSPLIT 4
#define KCHUNK (D_DIM / KSPLIT)   // 256

// Scratch (no cudaMalloc allowed)
__device__ float g_part[KSPLIT * B_DIM * H1_DIM];  // gemm1 partials (8 MB)
__device__ float g_pr0[B_DIM * H1_DIM];
__device__ float g_pr1[B_DIM * H1_DIM];

// ---------------------------------------------------------------------------
// Packed fp32x2 helpers (Blackwell FFMA2 — only reachable via PTX)
// ---------------------------------------------------------------------------
__device__ __forceinline__ unsigned long long pk2(float x, float y) {
    unsigned long long r;
    asm("mov.b64 %0, {%1, %2};" : "=l"(r) : "f"(x), "f"(y));
    return r;
}
__device__ __forceinline__ void ffma2(unsigned long long& d,
                                      unsigned long long a,
                                      unsigned long long b) {
    asm("fma.rn.f32x2 %0, %1, %2, %0;" : "+l"(d) : "l"(a), "l"(b));
}
__device__ __forceinline__ float2 upk2(unsigned long long v) {
    float2 f;
    asm("mov.b64 {%0, %1}, %2;" : "=f"(f.x), "=f"(f.y) : "l"(v));
    return f;
}

// ---------------------------------------------------------------------------
// Pipelined SGEMM with FFMA2: C[M,N](+z) = act(A[M,*] @ B[N,*]^T + bias)
// BM=32 (measured-best shape), BN=64, BK=32, 128 threads.
// grid = (M/32, N/64, SPLITZ). With SPLITZ>1 each z computes the K-chunk
// [z*Kloop, (z+1)*Kloop) and stores a raw partial into C + z*M*N.
// lda = row stride of A and Bm (full K).
// ---------------------------------------------------------------------------
template <bool RELU, bool WITH_BIAS, bool SPLITZ>
__global__ __launch_bounds__(128) void gemm_f2_kernel(
    const float* __restrict__ A, const float* __restrict__ Bm,
    const float* __restrict__ bias, float* __restrict__ C,
    int M, int N, int Kloop, int lda)
{
    constexpr int BM = 32, BK = 32;
    __shared__ float As[BM][BK + 1];
    __shared__ float Bs[BK][68];

    const int tid = threadIdx.x;
    const int tx = tid & 7;
    const int ty = tid >> 3;
    const int row0 = blockIdx.x * BM;
    const int col0 = blockIdx.y * 64;
    const int z = SPLITZ ? blockIdx.z : 0;

    const float* Ap = A + (size_t)z * Kloop;
    const float* Bp = Bm + (size_t)col0 * lda + (size_t)z * Kloop;
    float* Cz = C + (size_t)z * M * N;

    const int l_kq = tid & 7;
    const int l_r  = tid >> 3;

    unsigned long long acc[2][4];
#pragma unroll
    for (int i = 0; i < 2; i++)
#pragma unroll
        for (int j = 0; j < 4; j++) acc[i][j] = 0ull;

    const int NB = Kloop / BK;
    float4 pa[2], pb[4];

#pragma unroll
    for (int it = 0; it < 2; it++)
        pa[it] = *(const float4*)&Ap[(size_t)(row0 + l_r + it * 16) * lda + l_kq * 4];
#pragma unroll
    for (int it = 0; it < 4; it++)
        pb[it] = *(const float4*)&Bp[(size_t)(l_r + it * 16) * lda + l_kq * 4];

#pragma unroll
    for (int it = 0; it < 2; it++) {
        int r = l_r + it * 16;
        As[r][l_kq * 4 + 0] = pa[it].x; As[r][l_kq * 4 + 1] = pa[it].y;
        As[r][l_kq * 4 + 2] = pa[it].z; As[r][l_kq * 4 + 3] = pa[it].w;
    }
#pragma unroll
    for (int it = 0; it < 4; it++) {
        int f = l_r + it * 16;
        Bs[l_kq * 4 + 0][f] = pb[it].x; Bs[l_kq * 4 + 1][f] = pb[it].y;
        Bs[l_kq * 4 + 2][f] = pb[it].z; Bs[l_kq * 4 + 3][f] = pb[it].w;
    }
    __syncthreads();

    const int ty2 = ty * 2;
    for (int kb = 0; kb < NB; kb++) {
        const bool more = (kb + 1 < NB);
        if (more) {
            const int k0 = (kb + 1) * BK;
#pragma unroll
            for (int it = 0; it < 2; it++)
                pa[it] = *(const float4*)&Ap[(size_t)(row0 + l_r + it * 16) * lda + k0 + l_kq * 4];
#pragma unroll
            for (int it = 0; it < 4; it++)
                pb[it] = *(const float4*)&Bp[(size_t)(l_r + it * 16) * lda + k0 + l_kq * 4];
        }

#pragma unroll
        for (int kk = 0; kk < BK; kk++) {
            float a0 = As[ty2][kk];
            float a1 = As[ty2 + 1][kk];
            unsigned long long ap0 = pk2(a0, a0);
            unsigned long long ap1 = pk2(a1, a1);
            ulonglong2 b01 = *(const ulonglong2*)&Bs[kk][tx * 4];
            ulonglong2 b23 = *(const ulonglong2*)&Bs[kk][32 + tx * 4];
            ffma2(acc[0][0], ap0, b01.x); ffma2(acc[0][1], ap0, b01.y);
            ffma2(acc[0][2], ap0, b23.x); ffma2(acc[0][3], ap0, b23.y);
            ffma2(acc[1][0], ap1, b01.x); ffma2(acc[1][1], ap1, b01.y);
            ffma2(acc[1][2], ap1, b23.x); ffma2(acc[1][3], ap1, b23.y);
        }
        __syncthreads();
        if (more) {
#pragma unroll
            for (int it = 0; it < 2; it++) {
                int r = l_r + it * 16;
                As[r][l_kq * 4 + 0] = pa[it].x; As[r][l_kq * 4 + 1] = pa[it].y;
                As[r][l_kq * 4 + 2] = pa[it].z; As[r][l_kq * 4 + 3] = pa[it].w;
            }
#pragma unroll
            for (int it = 0; it < 4; it++) {
                int f = l_r + it * 16;
                Bs[l_kq * 4 + 0][f] = pb[it].x; Bs[l_kq * 4 + 1][f] = pb[it].y;
                Bs[l_kq * 4 + 2][f] = pb[it].z; Bs[l_kq * 4 + 3][f] = pb[it].w;
            }
            __syncthreads();
        }
    }

#pragma unroll
    for (int i = 0; i < 2; i++) {
        const int r = row0 + ty2 + i;
#pragma unroll
        for (int half = 0; half < 2; half++) {
            const int c = half * 32 + tx * 4;
            float2 p0 = upk2(acc[i][half * 2 + 0]);
            float2 p1 = upk2(acc[i][half * 2 + 1]);
            float4 v = make_float4(p0.x, p0.y, p1.x, p1.y);
            if (WITH_BIAS) {
                v.x += bias[col0 + c + 0];
                v.y += bias[col0 + c + 1];
                v.z += bias[col0 + c + 2];
                v.w += bias[col0 + c + 3];
            }
            if (RELU) {
                v.x = fmaxf(v.x, 0.0f); v.y = fmaxf(v.y, 0.0f);
                v.z = fmaxf(v.z, 0.0f); v.w = fmaxf(v.w, 0.0f);
            }
            *(float4*)&Cz[(size_t)r * N + col0 + c] = v;
        }
    }
}

// ---------------------------------------------------------------------------
// Per-feature 6-NN batch averaging, fused with the gemm1 K-split combine:
// h1[b][f] = relu(sum_z part_z[b][f] + b1[f]) computed on load (fixed
// summation order -> deterministic). One CTA per feature (128 CTAs, 1024 thr).
// Hybrid bitonic sort of 32-bit value bits (post-ReLU => unsigned-monotonic):
// j in {1,2} in-thread, j in {4..64} warp shuffles, j>=128 via smem.
// Rank recovered by binary search; greedy frontier walk gives the 6-NN mean.
// ---------------------------------------------------------------------------
__device__ __forceinline__ void ce_u32(unsigned int& a, unsigned int& b, bool up) {
    unsigned int mn = min(a, b), mx = max(a, b);
    a = up ? mn : mx;
    b = up ? mx : mn;
}

__global__ __launch_bounds__(1024) void knn_mean_kernel(
    const float* __restrict__ part, const float* __restrict__ b1,
    float* __restrict__ out)
{
    __shared__ unsigned int sv[B_DIM];  // 16 KB

    const int f = blockIdx.x;
    const int t = threadIdx.x;
    const int lane = t & 31;
    const unsigned int i0 = 4u * (unsigned)t;
    const float biasf = b1[f];

    unsigned int v[4], myv[4];
#pragma unroll
    for (int e = 0; e < 4; e++) {
        const size_t idx = (size_t)(i0 + e) * H1_DIM + f;
        float s = part[idx];
        s += part[idx + (size_t)1 * B_DIM * H1_DIM];
        s += part[idx + (size_t)2 * B_DIM * H1_DIM];
        s += part[idx + (size_t)3 * B_DIM * H1_DIM];
        float h = fmaxf(s + biasf, 0.0f);
        v[e] = __float_as_uint(h);
        myv[e] = v[e];
    }

    // k = 2: pair (0,1) ascending, pair (2,3) descending
    {
        if (v[0] > v[1]) { unsigned int tm = v[0]; v[0] = v[1]; v[1] = tm; }
        if (v[2] < v[3]) { unsigned int tm = v[2]; v[2] = v[3]; v[3] = tm; }
    }
    // k = 4: dir = (t&1)==0; phases j=2 then j=1 (both in-thread)
    {
        bool up = (t & 1) == 0;
        ce_u32(v[0], v[2], up); ce_u32(v[1], v[3], up);
        ce_u32(v[0], v[1], up); ce_u32(v[2], v[3], up);
    }

    for (unsigned int k = 8; k <= B_DIM; k <<= 1) {
        const bool up = ((i0 & k) == 0);
        unsigned int j = k >> 1;

        // --- smem phases: j >= 128 (cross-warp partners) ---
        if (j >= 128) {
            *(uint4*)&sv[i0] = make_uint4(v[0], v[1], v[2], v[3]);
            __syncthreads();
            for (; j >= 128; j >>= 1) {
#pragma unroll 2
                for (int p = t; p < B_DIM / 2; p += 1024) {
                    int i = ((p & ~(int)(j - 1)) << 1) | (p & (int)(j - 1));
                    int ixj = i | (int)j;
                    unsigned int a = sv[i];
                    unsigned int b = sv[ixj];
                    bool u2 = ((i & (int)k) == 0);
                    if (u2 ? (a > b) : (a < b)) { sv[i] = b; sv[ixj] = a; }
                }
                __syncthreads();
            }
            uint4 u = *(const uint4*)&sv[i0];
            v[0] = u.x; v[1] = u.y; v[2] = u.z; v[3] = u.w;
        }

        // --- shuffle phases: 64 >= j >= 4 (partner lane = lane ^ (j/4)) ---
        for (; j >= 4; j >>= 1) {
            const unsigned int d = j >> 2;
            const bool keepmin = (up == ((lane & d) == 0));
#pragma unroll
            for (int e = 0; e < 4; e++) {
                unsigned int o = __shfl_xor_sync(0xFFFFFFFFu, v[e], d);
                unsigned int mn = min(v[e], o), mx = max(v[e], o);
                v[e] = keepmin ? mn : mx;
            }
        }

        // --- in-thread phases: j = 2 then j = 1 ---
        ce_u32(v[0], v[2], up); ce_u32(v[1], v[3], up);
        ce_u32(v[0], v[1], up); ce_u32(v[2], v[3], up);
    }

    // Publish sorted array
    *(uint4*)&sv[i0] = make_uint4(v[0], v[1], v[2], v[3]);
    __syncthreads();

    const float BIG = __int_as_float(0x7f000000);

#pragma unroll
    for (int e = 0; e < 4; e++) {
        const int b = (int)i0 + e;
        const unsigned int vb = myv[e];
        // lower_bound over 4096 sorted keys: exactly 12 halvings
        int lo = 0, hi = B_DIM;
#pragma unroll
        for (int s = 0; s < 12; s++) {
            int mid = (lo + hi) >> 1;
            if (sv[mid] < vb) lo = mid + 1; else hi = mid;
        }
        int p = lo;  // sv[p] == vb
        float val = __uint_as_float(vb);
        float sum = val;
        int l = p - 1, r = p + 1;
#pragma unroll
        for (int s = 0; s < 5; s++) {
            float vl = (l >= 0)     ? __uint_as_float(sv[l]) : 0.0f;
            float vr = (r < B_DIM)  ? __uint_as_float(sv[r]) : 0.0f;
            float dl = (l >= 0)     ? (val - vl) : BIG;
            float dr = (r < B_DIM)  ? (vr - val) : BIG;
            if (dl <= dr) { sum += vl; l--; }
            else          { sum += vr; r++; }
        }
        out[(size_t)b * H1_DIM + f] = sum * (1.0f / 6.0f);
    }
}

// ---------------------------------------------------------------------------
// Fused tail: h2 = relu(pr1 @ W2^T + b2); out = h2 @ Wo^T + bo
// Pipelined gemm (BM=32, N=64, K=128), 128 CTAs x 128 threads. Measured 11.7us.
// ---------------------------------------------------------------------------
__global__ __launch_bounds__(128) void tail_fused_kernel(
    const float* __restrict__ A,    // pr1 [4096,128]
    const float* __restrict__ W2,   // [64,128]
    const float* __restrict__ b2,   // [64]
    const float* __restrict__ Wo,   // [2,64]
    const float* __restrict__ bo,   // [2]
    float* __restrict__ out)        // [4096,2]
{
    constexpr int BM = 32, BK = 32, K = H1_DIM, NB = K / BK;
    __shared__ float As[BM][BK + 1];
    __shared__ float Bs[BK][68];
    __shared__ float h2s[BM][H2_DIM + 1];
    __shared__ float wos[O_DIM * H2_DIM];
    __shared__ float b2s[H2_DIM];
    __shared__ float bos[O_DIM];

    const int tid = threadIdx.x;
    const int tx = tid & 7;
    const int ty = tid >> 3;
    const int row0 = blockIdx.x * BM;

    const int l_kq = tid & 7;
    const int l_r  = tid >> 3;

    wos[tid] = Wo[tid];
    if (tid < H2_DIM) b2s[tid] = b2[tid];
    if (tid < O_DIM)  bos[tid] = bo[tid];

    unsigned long long acc[2][4];
#pragma unroll
    for (int i = 0; i < 2; i++)
#pragma unroll
        for (int j = 0; j < 4; j++) acc[i][j] = 0ull;

    float4 pa[2], pb[4];
#pragma unroll
    for (int it = 0; it < 2; it++)
        pa[it] = *(const float4*)&A[(size_t)(row0 + l_r + it * 16) * K + l_kq * 4];
#pragma unroll
    for (int it = 0; it < 4; it++)
        pb[it] = *(const float4*)&W2[(size_t)(l_r + it * 16) * K + l_kq * 4];

#pragma unroll
    for (int it = 0; it < 2; it++) {
        int r = l_r + it * 16;
        As[r][l_kq * 4 + 0] = pa[it].x; As[r][l_kq * 4 + 1] = pa[it].y;
        As[r][l_kq * 4 + 2] = pa[it].z; As[r][l_kq * 4 + 3] = pa[it].w;
    }
#pragma unroll
    for (int it = 0; it < 4; it++) {
        int c = l_r + it * 16;
        Bs[l_kq * 4 + 0][c] = pb[it].x; Bs[l_kq * 4 + 1][c] = pb[it].y;
        Bs[l_kq * 4 + 2][c] = pb[it].z; Bs[l_kq * 4 + 3][c] = pb[it].w;
    }
    __syncthreads();

    const int ty2 = ty * 2;
#pragma unroll
    for (int kb = 0; kb < NB; kb++) {
        const bool more = (kb + 1 < NB);
        if (more) {
            const int k0 = (kb + 1) * BK;
#pragma unroll
            for (int it = 0; it < 2; it++)
                pa[it] = *(const float4*)&A[(size_t)(row0 + l_r + it * 16) * K + k0 + l_kq * 4];
#pragma unroll
            for (int it = 0; it < 4; it++)
                pb[it] = *(const float4*)&W2[(size_t)(l_r + it * 16) * K + k0 + l_kq * 4];
        }
#pragma unroll
        for (int kk = 0; kk < BK; kk++) {
            float a0 = As[ty2][kk];
            float a1 = As[ty2 + 1][kk];
            unsigned long long ap0 = pk2(a0, a0);
            unsigned long long ap1 = pk2(a1, a1);
            ulonglong2 b01 = *(const ulonglong2*)&Bs[kk][tx * 4];
            ulonglong2 b23 = *(const ulonglong2*)&Bs[kk][32 + tx * 4];
            ffma2(acc[0][0], ap0, b01.x); ffma2(acc[0][1], ap0, b01.y);
            ffma2(acc[0][2], ap0, b23.x); ffma2(acc[0][3], ap0, b23.y);
            ffma2(acc[1][0], ap1, b01.x); ffma2(acc[1][1], ap1, b01.y);
            ffma2(acc[1][2], ap1, b23.x); ffma2(acc[1][3], ap1, b23.y);
        }
        __syncthreads();
        if (more) {
#pragma unroll
            for (int it = 0; it < 2; it++) {
                int r = l_r + it * 16;
                As[r][l_kq * 4 + 0] = pa[it].x; As[r][l_kq * 4 + 1] = pa[it].y;
                As[r][l_kq * 4 + 2] = pa[it].z; As[r][l_kq * 4 + 3] = pa[it].w;
            }
#pragma unroll
            for (int it = 0; it < 4; it++) {
                int c = l_r + it * 16;
                Bs[l_kq * 4 + 0][c] = pb[it].x; Bs[l_kq * 4 + 1][c] = pb[it].y;
                Bs[l_kq * 4 + 2][c] = pb[it].z; Bs[l_kq * 4 + 3][c] = pb[it].w;
            }
            __syncthreads();
        }
    }

    // h2 tile -> smem with bias + ReLU
#pragma unroll
    for (int i = 0; i < 2; i++) {
        const int r = ty2 + i;
#pragma unroll
        for (int half = 0; half < 2; half++) {
            const int c = half * 32 + tx * 4;
            float2 p0 = upk2(acc[i][half * 2 + 0]);
            float2 p1 = upk2(acc[i][half * 2 + 1]);
            h2s[r][c + 0] = fmaxf(p0.x + b2s[c + 0], 0.0f);
            h2s[r][c + 1] = fmaxf(p0.y + b2s[c + 1], 0.0f);
            h2s[r][c + 2] = fmaxf(p1.x + b2s[c + 2], 0.0f);
            h2s[r][c + 3] = fmaxf(p1.y + b2s[c + 3], 0.0f);
        }
    }
    __syncthreads();

    // Projection: 64 work items (32 rows x 2 outs)
    if (tid < BM * O_DIM) {
        int r = tid >> 1, o = tid & 1;
        float s = 0.0f;
        const float* w = &wos[o * H2_DIM];
#pragma unroll
        for (int k = 0; k < H2_DIM; k++)
            s = fmaf(h2s[r][k], w[k], s);
        out[(size_t)(row0 + r) * O_DIM + o] = s + bos[o];
    }
}

// ---------------------------------------------------------------------------
extern "C" void kernel_launch(void* const* d_in, const int* in_sizes, int n_in,
                              void* d_out, int out_size)
{
    const float* x   = (const float*)d_in[0];
    const float* W1  = (const float*)d_in[1];
    const float* b1  = (const float*)d_in[2];
    const float* Wpr = (const float*)d_in[3];
    const float* bpr = (const float*)d_in[4];
    const float* W2  = (const float*)d_in[5];
    const float* b2  = (const float*)d_in[6];
    const float* Wo  = (const float*)d_in[7];
    const float* bo  = (const float*)d_in[8];
    float* out = (float*)d_out;

    float *part, *pr0, *pr1;
    cudaGetSymbolAddress((void**)&part, g_part);
    cudaGetSymbolAddress((void**)&pr0,  g_pr0);
    cudaGetSymbolAddress((void**)&pr1,  g_pr1);

    // 1) gemm1 K-split: part[z] = x @ W1^T over K-chunk z  (1024 CTAs)
    gemm_f2_kernel<false, false, true>
        <<<dim3(B_DIM / 32, H1_DIM / 64, KSPLIT), 128>>>(
        x, W1, nullptr, part, B_DIM, H1_DIM, KCHUNK, D_DIM);
    // 2) knn: fused combine (sum partials + b1, relu) + 6-NN mean
    knn_mean_kernel<<<H1_DIM, 1024>>>(part, b1, pr0);
    // 3) pr1 = relu(pr0 @ Wpr^T + bpr)   [4096,128], K=128, 256 CTAs
    gemm_f2_kernel<true, true, false>
        <<<dim3(B_DIM / 32, H1_DIM / 64, 1), 128>>>(
        pr0, Wpr, bpr, pr1, B_DIM, H1_DIM, H1_DIM, H1_DIM);
    // 4) fused h2 + output projection
    tail_fused_kernel<<<B_DIM / 32, 128>>>(pr1, W2, b2, Wo, bo, out);
}

// round 12
// speedup vs baseline: 1.7551x; 1.0845x over previous
#include <cuda_runtime.h>
#include <cuda_bf16.h>
#include <cstdint>

#define B_DIM 4096
#define D_DIM 1024
#define H1_DIM 128
#define H2_DIM 64
#define O_DIM 2
#define KSPLIT 4
#define KCHUNK (D_DIM / KSPLIT)   // 256

// Scratch (no cudaMalloc allowed)
__device__ float g_part[KSPLIT * B_DIM * H1_DIM];  // gemm1 partials (8 MB)
__device__ float g_h1T[H1_DIM * B_DIM];            // h1 transposed [f][b]
__device__ float g_pr0T[H1_DIM * B_DIM];           // knn output transposed [f][b]
__device__ float g_pr1[B_DIM * H1_DIM];            // row-major for tail

// ---------------------------------------------------------------------------
// Packed fp32x2 helpers (Blackwell FFMA2 — only reachable via PTX)
// ---------------------------------------------------------------------------
__device__ __forceinline__ unsigned long long pk2(float x, float y) {
    unsigned long long r;
    asm("mov.b64 %0, {%1, %2};" : "=l"(r) : "f"(x), "f"(y));
    return r;
}
__device__ __forceinline__ void ffma2(unsigned long long& d,
                                      unsigned long long a,
                                      unsigned long long b) {
    asm("fma.rn.f32x2 %0, %1, %2, %0;" : "+l"(d) : "l"(a), "l"(b));
}
__device__ __forceinline__ float2 upk2(unsigned long long v) {
    float2 f;
    asm("mov.b64 {%0, %1}, %2;" : "=f"(f.x), "=f"(f.y) : "l"(v));
    return f;
}

// ---------------------------------------------------------------------------
// Pipelined SGEMM with FFMA2 (NN, A row-major K-major): used for gemm1 K-split.
// BM=32, BN=64, BK=32, 128 threads. grid=(M/32, N/64, KSPLIT).
// Each z computes K-chunk [z*Kloop, (z+1)*Kloop) -> raw partial at C + z*M*N.
// ---------------------------------------------------------------------------
__global__ __launch_bounds__(128) void gemm_split_kernel(
    const float* __restrict__ A, const float* __restrict__ Bm,
    float* __restrict__ C, int M, int N, int Kloop, int lda)
{
    constexpr int BM = 32, BK = 32;
    __shared__ float As[BM][BK + 1];
    __shared__ float Bs[BK][68];

    const int tid = threadIdx.x;
    const int tx = tid & 7;
    const int ty = tid >> 3;
    const int row0 = blockIdx.x * BM;
    const int col0 = blockIdx.y * 64;
    const int z = blockIdx.z;

    const float* Ap = A + (size_t)z * Kloop;
    const float* Bp = Bm + (size_t)col0 * lda + (size_t)z * Kloop;
    float* Cz = C + (size_t)z * M * N;

    const int l_kq = tid & 7;
    const int l_r  = tid >> 3;

    unsigned long long acc[2][4];
#pragma unroll
    for (int i = 0; i < 2; i++)
#pragma unroll
        for (int j = 0; j < 4; j++) acc[i][j] = 0ull;

    const int NB = Kloop / BK;
    float4 pa[2], pb[4];

#pragma unroll
    for (int it = 0; it < 2; it++)
        pa[it] = *(const float4*)&Ap[(size_t)(row0 + l_r + it * 16) * lda + l_kq * 4];
#pragma unroll
    for (int it = 0; it < 4; it++)
        pb[it] = *(const float4*)&Bp[(size_t)(l_r + it * 16) * lda + l_kq * 4];

#pragma unroll
    for (int it = 0; it < 2; it++) {
        int r = l_r + it * 16;
        As[r][l_kq * 4 + 0] = pa[it].x; As[r][l_kq * 4 + 1] = pa[it].y;
        As[r][l_kq * 4 + 2] = pa[it].z; As[r][l_kq * 4 + 3] = pa[it].w;
    }
#pragma unroll
    for (int it = 0; it < 4; it++) {
        int f = l_r + it * 16;
        Bs[l_kq * 4 + 0][f] = pb[it].x; Bs[l_kq * 4 + 1][f] = pb[it].y;
        Bs[l_kq * 4 + 2][f] = pb[it].z; Bs[l_kq * 4 + 3][f] = pb[it].w;
    }
    __syncthreads();

    const int ty2 = ty * 2;
    for (int kb = 0; kb < NB; kb++) {
        const bool more = (kb + 1 < NB);
        if (more) {
            const int k0 = (kb + 1) * BK;
#pragma unroll
            for (int it = 0; it < 2; it++)
                pa[it] = *(const float4*)&Ap[(size_t)(row0 + l_r + it * 16) * lda + k0 + l_kq * 4];
#pragma unroll
            for (int it = 0; it < 4; it++)
                pb[it] = *(const float4*)&Bp[(size_t)(l_r + it * 16) * lda + k0 + l_kq * 4];
        }

#pragma unroll
        for (int kk = 0; kk < BK; kk++) {
            float a0 = As[ty2][kk];
            float a1 = As[ty2 + 1][kk];
            unsigned long long ap0 = pk2(a0, a0);
            unsigned long long ap1 = pk2(a1, a1);
            ulonglong2 b01 = *(const ulonglong2*)&Bs[kk][tx * 4];
            ulonglong2 b23 = *(const ulonglong2*)&Bs[kk][32 + tx * 4];
            ffma2(acc[0][0], ap0, b01.x); ffma2(acc[0][1], ap0, b01.y);
            ffma2(acc[0][2], ap0, b23.x); ffma2(acc[0][3], ap0, b23.y);
            ffma2(acc[1][0], ap1, b01.x); ffma2(acc[1][1], ap1, b01.y);
            ffma2(acc[1][2], ap1, b23.x); ffma2(acc[1][3], ap1, b23.y);
        }
        __syncthreads();
        if (more) {
#pragma unroll
            for (int it = 0; it < 2; it++) {
                int r = l_r + it * 16;
                As[r][l_kq * 4 + 0] = pa[it].x; As[r][l_kq * 4 + 1] = pa[it].y;
                As[r][l_kq * 4 + 2] = pa[it].z; As[r][l_kq * 4 + 3] = pa[it].w;
            }
#pragma unroll
            for (int it = 0; it < 4; it++) {
                int f = l_r + it * 16;
                Bs[l_kq * 4 + 0][f] = pb[it].x; Bs[l_kq * 4 + 1][f] = pb[it].y;
                Bs[l_kq * 4 + 2][f] = pb[it].z; Bs[l_kq * 4 + 3][f] = pb[it].w;
            }
            __syncthreads();
        }
    }

#pragma unroll
    for (int i = 0; i < 2; i++) {
        const int r = row0 + ty2 + i;
#pragma unroll
        for (int half = 0; half < 2; half++) {
            const int c = half * 32 + tx * 4;
            float2 p0 = upk2(acc[i][half * 2 + 0]);
            float2 p1 = upk2(acc[i][half * 2 + 1]);
            *(float4*)&Cz[(size_t)r * N + col0 + c] =
                make_float4(p0.x, p0.y, p1.x, p1.y);
        }
    }
}

// ---------------------------------------------------------------------------
// Combine K-split partials + bias + ReLU, writing h1 TRANSPOSED:
// h1T[f][b] = relu(sum_z part_z[b][f] + b1[f]).
// All global accesses coalesced; 32x33 smem tile for the transpose.
// grid (B/32, F/32), 256 threads.
// ---------------------------------------------------------------------------
__global__ __launch_bounds__(256) void combine_transpose_kernel(
    const float* __restrict__ part, const float* __restrict__ b1,
    float* __restrict__ h1T)
{
    __shared__ float t[32][33];
    const int bx = blockIdx.x * 32;
    const int fx = blockIdx.y * 32;
    const int tid = threadIdx.x;
    const int x = tid & 7;     // float4 index along f
    const int y = tid >> 3;    // row (b) within tile

    const size_t BH = (size_t)B_DIM * H1_DIM;
    const size_t idx = (size_t)(bx + y) * H1_DIM + fx + x * 4;
    float4 s  = *(const float4*)&part[idx];
    float4 p1 = *(const float4*)&part[idx + BH];
    float4 p2 = *(const float4*)&part[idx + 2 * BH];
    float4 p3 = *(const float4*)&part[idx + 3 * BH];
    s.x += p1.x; s.y += p1.y; s.z += p1.z; s.w += p1.w;
    s.x += p2.x; s.y += p2.y; s.z += p2.z; s.w += p2.w;
    s.x += p3.x; s.y += p3.y; s.z += p3.z; s.w += p3.w;
    const float4 bv = *(const float4*)&b1[fx + x * 4];
    t[y][x * 4 + 0] = fmaxf(s.x + bv.x, 0.0f);
    t[y][x * 4 + 1] = fmaxf(s.y + bv.y, 0.0f);
    t[y][x * 4 + 2] = fmaxf(s.z + bv.z, 0.0f);
    t[y][x * 4 + 3] = fmaxf(s.w + bv.w, 0.0f);
    __syncthreads();

    // write h1T[fx+y][bx + x*4 .. +3] = t[x*4+e][y]  (conflict-free reads)
    float4 o;
    o.x = t[x * 4 + 0][y];
    o.y = t[x * 4 + 1][y];
    o.z = t[x * 4 + 2][y];
    o.w = t[x * 4 + 3][y];
    *(float4*)&h1T[(size_t)(fx + y) * B_DIM + bx + x * 4] = o;
}

// ---------------------------------------------------------------------------
// Per-feature 6-NN batch averaging on TRANSPOSED layout (fully coalesced I/O).
// One CTA per feature (128 CTAs, 1024 thr). Hybrid bitonic sort of 32-bit
// value bits (post-ReLU => unsigned-monotonic): j in {1,2} in-thread,
// j in {4..64} warp shuffles, j>=128 via smem. Rank via binary search;
// greedy frontier walk gives the 6-NN mean.
// ---------------------------------------------------------------------------
__device__ __forceinline__ void ce_u32(unsigned int& a, unsigned int& b, bool up) {
    unsigned int mn = min(a, b), mx = max(a, b);
    a = up ? mn : mx;
    b = up ? mx : mn;
}

__global__ __launch_bounds__(1024) void knn_mean_kernel(
    const float* __restrict__ h1T, float* __restrict__ outT)
{
    __shared__ unsigned int sv[B_DIM];  // 16 KB

    const int f = blockIdx.x;
    const int t = threadIdx.x;
    const int lane = t & 31;
    const unsigned int i0 = 4u * (unsigned)t;

    unsigned int v[4], myv[4];
    {
        const uint4 hv = *(const uint4*)&h1T[(size_t)f * B_DIM + i0];
        v[0] = hv.x; v[1] = hv.y; v[2] = hv.z; v[3] = hv.w;
#pragma unroll
        for (int e = 0; e < 4; e++) myv[e] = v[e];
    }

    // k = 2: pair (0,1) ascending, pair (2,3) descending
    {
        if (v[0] > v[1]) { unsigned int tm = v[0]; v[0] = v[1]; v[1] = tm; }
        if (v[2] < v[3]) { unsigned int tm = v[2]; v[2] = v[3]; v[3] = tm; }
    }
    // k = 4: dir = (t&1)==0; phases j=2 then j=1 (both in-thread)
    {
        bool up = (t & 1) == 0;
        ce_u32(v[0], v[2], up); ce_u32(v[1], v[3], up);
        ce_u32(v[0], v[1], up); ce_u32(v[2], v[3], up);
    }

    for (unsigned int k = 8; k <= B_DIM; k <<= 1) {
        const bool up = ((i0 & k) == 0);
        unsigned int j = k >> 1;

        // --- smem phases: j >= 128 (cross-warp partners) ---
        if (j >= 128) {
            *(uint4*)&sv[i0] = make_uint4(v[0], v[1], v[2], v[3]);
            __syncthreads();
            for (; j >= 128; j >>= 1) {
#pragma unroll 2
                for (int p = t; p < B_DIM / 2; p += 1024) {
                    int i = ((p & ~(int)(j - 1)) << 1) | (p & (int)(j - 1));
                    int ixj = i | (int)j;
                    unsigned int a = sv[i];
                    unsigned int b = sv[ixj];
                    bool u2 = ((i & (int)k) == 0);
                    if (u2 ? (a > b) : (a < b)) { sv[i] = b; sv[ixj] = a; }
                }
                __syncthreads();
            }
            uint4 u = *(const uint4*)&sv[i0];
            v[0] = u.x; v[1] = u.y; v[2] = u.z; v[3] = u.w;
        }

        // --- shuffle phases: 64 >= j >= 4 (partner lane = lane ^ (j/4)) ---
        for (; j >= 4; j >>= 1) {
            const unsigned int d = j >> 2;
            const bool keepmin = (up == ((lane & d) == 0));
#pragma unroll
            for (int e = 0; e < 4; e++) {
                unsigned int o = __shfl_xor_sync(0xFFFFFFFFu, v[e], d);
                unsigned int mn = min(v[e], o), mx = max(v[e], o);
                v[e] = keepmin ? mn : mx;
            }
        }

        // --- in-thread phases: j = 2 then j = 1 ---
        ce_u32(v[0], v[2], up); ce_u32(v[1], v[3], up);
        ce_u32(v[0], v[1], up); ce_u32(v[2], v[3], up);
    }

    // Publish sorted array
    *(uint4*)&sv[i0] = make_uint4(v[0], v[1], v[2], v[3]);
    __syncthreads();

    const float BIG = __int_as_float(0x7f000000);
    float res[4];

#pragma unroll
    for (int e = 0; e < 4; e++) {
        const unsigned int vb = myv[e];
        // lower_bound over 4096 sorted keys: exactly 12 halvings
        int lo = 0, hi = B_DIM;
#pragma unroll
        for (int s = 0; s < 12; s++) {
            int mid = (lo + hi) >> 1;
            if (sv[mid] < vb) lo = mid + 1; else hi = mid;
        }
        int p = lo;  // sv[p] == vb
        float val = __uint_as_float(vb);
        float sum = val;
        int l = p - 1, r = p + 1;
#pragma unroll
        for (int s = 0; s < 5; s++) {
            float vl = (l >= 0)     ? __uint_as_float(sv[l]) : 0.0f;
            float vr = (r < B_DIM)  ? __uint_as_float(sv[r]) : 0.0f;
            float dl = (l >= 0)     ? (val - vl) : BIG;
            float dr = (r < B_DIM)  ? (vr - val) : BIG;
            if (dl <= dr) { sum += vl; l--; }
            else          { sum += vr; r++; }
        }
        res[e] = sum * (1.0f / 6.0f);
    }

    *(float4*)&outT[(size_t)f * B_DIM + i0] =
        make_float4(res[0], res[1], res[2], res[3]);
}

// ---------------------------------------------------------------------------
// TN GEMM with FFMA2: C[M,N] = relu(AT^T @ B^T + bias), AT = [K][M] (pr0T).
// BM=32, BN=64, BK=32, 128 threads. grid=(M/32, N/64). A-tile is naturally
// [k][m] in smem (no transpose needed); A operand fetch is one LDS.64.
// ---------------------------------------------------------------------------
__global__ __launch_bounds__(128) void gemm_tn_kernel(
    const float* __restrict__ AT,   // [K=128][M=4096]
    const float* __restrict__ Bm,   // Wpr [N=128][K=128] (K-major)
    const float* __restrict__ bias, float* __restrict__ C,
    int M, int N, int K)
{
    constexpr int BM = 32, BK = 32;
    __shared__ float As2[BK][BM + 2];   // [k][m], stride 34 (8B-aligned pairs)
    __shared__ float Bs[BK][68];

    const int tid = threadIdx.x;
    const int tx = tid & 7;
    const int ty = tid >> 3;
    const int row0 = blockIdx.x * BM;
    const int col0 = blockIdx.y * 64;
    const float* Bp = Bm + (size_t)col0 * K;

    const int l_kq = tid & 7;
    const int l_r  = tid >> 3;

    unsigned long long acc[2][4];
#pragma unroll
    for (int i = 0; i < 2; i++)
#pragma unroll
        for (int j = 0; j < 4; j++) acc[i][j] = 0ull;

    const int NB = K / BK;
    float4 pa[2], pb[4];

#pragma unroll
    for (int it = 0; it < 2; it++)
        pa[it] = *(const float4*)&AT[(size_t)(l_r + it * 16) * M + row0 + l_kq * 4];
#pragma unroll
    for (int it = 0; it < 4; it++)
        pb[it] = *(const float4*)&Bp[(size_t)(l_r + it * 16) * K + l_kq * 4];

#pragma unroll
    for (int it = 0; it < 2; it++) {
        int kr = l_r + it * 16;
        As2[kr][l_kq * 4 + 0] = pa[it].x; As2[kr][l_kq * 4 + 1] = pa[it].y;
        As2[kr][l_kq * 4 + 2] = pa[it].z; As2[kr][l_kq * 4 + 3] = pa[it].w;
    }
#pragma unroll
    for (int it = 0; it < 4; it++) {
        int f = l_r + it * 16;
        Bs[l_kq * 4 + 0][f] = pb[it].x; Bs[l_kq * 4 + 1][f] = pb[it].y;
        Bs[l_kq * 4 + 2][f] = pb[it].z; Bs[l_kq * 4 + 3][f] = pb[it].w;
    }
    __syncthreads();

    const int ty2 = ty * 2;
    for (int kb = 0; kb < NB; kb++) {
        const bool more = (kb + 1 < NB);
        if (more) {
            const int k0 = (kb + 1) * BK;
#pragma unroll
            for (int it = 0; it < 2; it++)
                pa[it] = *(const float4*)&AT[(size_t)(k0 + l_r + it * 16) * M + row0 + l_kq * 4];
#pragma unroll
            for (int it = 0; it < 4; it++)
                pb[it] = *(const float4*)&Bp[(size_t)(l_r + it * 16) * K + k0 + l_kq * 4];
        }

#pragma unroll
        for (int kk = 0; kk < BK; kk++) {
            float2 a = *(const float2*)&As2[kk][ty2];
            unsigned long long ap0 = pk2(a.x, a.x);
            unsigned long long ap1 = pk2(a.y, a.y);
            ulonglong2 b01 = *(const ulonglong2*)&Bs[kk][tx * 4];
            ulonglong2 b23 = *(const ulonglong2*)&Bs[kk][32 + tx * 4];
            ffma2(acc[0][0], ap0, b01.x); ffma2(acc[0][1], ap0, b01.y);
            ffma2(acc[0][2], ap0, b23.x); ffma2(acc[0][3], ap0, b23.y);
            ffma2(acc[1][0], ap1, b01.x); ffma2(acc[1][1], ap1, b01.y);
            ffma2(acc[1][2], ap1, b23.x); ffma2(acc[1][3], ap1, b23.y);
        }
        __syncthreads();
        if (more) {
#pragma unroll
            for (int it = 0; it < 2; it++) {
                int kr = l_r + it * 16;
                As2[kr][l_kq * 4 + 0] = pa[it].x; As2[kr][l_kq * 4 + 1] = pa[it].y;
                As2[kr][l_kq * 4 + 2] = pa[it].z; As2[kr][l_kq * 4 + 3] = pa[it].w;
            }
#pragma unroll
            for (int it = 0; it < 4; it++) {
                int f = l_r + it * 16;
                Bs[l_kq * 4 + 0][f] = pb[it].x; Bs[l_kq * 4 + 1][f] = pb[it].y;
                Bs[l_kq * 4 + 2][f] = pb[it].z; Bs[l_kq * 4 + 3][f] = pb[it].w;
            }
            __syncthreads();
        }
    }

#pragma unroll
    for (int i = 0; i < 2; i++) {
        const int r = row0 + ty2 + i;
#pragma unroll
        for (int half = 0; half < 2; half++) {
            const int c = half * 32 + tx * 4;
            float2 p0 = upk2(acc[i][half * 2 + 0]);
            float2 p1 = upk2(acc[i][half * 2 + 1]);
            float4 v;
            v.x = fmaxf(p0.x + bias[col0 + c + 0], 0.0f);
            v.y = fmaxf(p0.y + bias[col0 + c + 1], 0.0f);
            v.z = fmaxf(p1.x + bias[col0 + c + 2], 0.0f);
            v.w = fmaxf(p1.y + bias[col0 + c + 3], 0.0f);
            *(float4*)&C[(size_t)r * N + col0 + c] = v;
        }
    }
}

// ---------------------------------------------------------------------------
// Fused tail: h2 = relu(pr1 @ W2^T + b2); out = h2 @ Wo^T + bo
// Pipelined gemm (BM=32, N=64, K=128), 128 CTAs x 128 threads. Measured 11.5us.
// ---------------------------------------------------------------------------
__global__ __launch_bounds__(128) void tail_fused_kernel(
    const float* __restrict__ A,    // pr1 [4096,128]
    const float* __restrict__ W2,   // [64,128]
    const float* __restrict__ b2,   // [64]
    const float* __restrict__ Wo,   // [2,64]
    const float* __restrict__ bo,   // [2]
    float* __restrict__ out)        // [4096,2]
{
    constexpr int BM = 32, BK = 32, K = H1_DIM, NB = K / BK;
    __shared__ float As[BM][BK + 1];
    __shared__ float Bs[BK][68];
    __shared__ float h2s[BM][H2_DIM + 1];
    __shared__ float wos[O_DIM * H2_DIM];
    __shared__ float b2s[H2_DIM];
    __shared__ float bos[O_DIM];

    const int tid = threadIdx.x;
    const int tx = tid & 7;
    const int ty = tid >> 3;
    const int row0 = blockIdx.x * BM;

    const int l_kq = tid & 7;
    const int l_r  = tid >> 3;

    wos[tid] = Wo[tid];
    if (tid < H2_DIM) b2s[tid] = b2[tid];
    if (tid < O_DIM)  bos[tid] = bo[tid];

    unsigned long long acc[2][4];
#pragma unroll
    for (int i = 0; i < 2; i++)
#pragma unroll
        for (int j = 0; j < 4; j++) acc[i][j] = 0ull;

    float4 pa[2], pb[4];
#pragma unroll
    for (int it = 0; it < 2; it++)
        pa[it] = *(const float4*)&A[(size_t)(row0 + l_r + it * 16) * K + l_kq * 4];
#pragma unroll
    for (int it = 0; it < 4; it++)
        pb[it] = *(const float4*)&W2[(size_t)(l_r + it * 16) * K + l_kq * 4];

#pragma unroll
    for (int it = 0; it < 2; it++) {
        int r = l_r + it * 16;
        As[r][l_kq * 4 + 0] = pa[it].x; As[r][l_kq * 4 + 1] = pa[it].y;
        As[r][l_kq * 4 + 2] = pa[it].z; As[r][l_kq * 4 + 3] = pa[it].w;
    }
#pragma unroll
    for (int it = 0; it < 4; it++) {
        int c = l_r + it * 16;
        Bs[l_kq * 4 + 0][c] = pb[it].x; Bs[l_kq * 4 + 1][c] = pb[it].y;
        Bs[l_kq * 4 + 2][c] = pb[it].z; Bs[l_kq * 4 + 3][c] = pb[it].w;
    }
    __syncthreads();

    const int ty2 = ty * 2;
#pragma unroll
    for (int kb = 0; kb < NB; kb++) {
        const bool more = (kb + 1 < NB);
        if (more) {
            const int k0 = (kb + 1) * BK;
#pragma unroll
            for (int it = 0; it < 2; it++)
                pa[it] = *(const float4*)&A[(size_t)(row0 + l_r + it * 16) * K + k0 + l_kq * 4];
#pragma unroll
            for (int it = 0; it < 4; it++)
                pb[it] = *(const float4*)&W2[(size_t)(l_r + it * 16) * K + k0 + l_kq * 4];
        }
#pragma unroll
        for (int kk = 0; kk < BK; kk++) {
            float a0 = As[ty2][kk];
            float a1 = As[ty2 + 1][kk];
            unsigned long long ap0 = pk2(a0, a0);
            unsigned long long ap1 = pk2(a1, a1);
            ulonglong2 b01 = *(const ulonglong2*)&Bs[kk][tx * 4];
            ulonglong2 b23 = *(const ulonglong2*)&Bs[kk][32 + tx * 4];
            ffma2(acc[0][0], ap0, b01.x); ffma2(acc[0][1], ap0, b01.y);
            ffma2(acc[0][2], ap0, b23.x); ffma2(acc[0][3], ap0, b23.y);
            ffma2(acc[1][0], ap1, b01.x); ffma2(acc[1][1], ap1, b01.y);
            ffma2(acc[1][2], ap1, b23.x); ffma2(acc[1][3], ap1, b23.y);
        }
        __syncthreads();
        if (more) {
#pragma unroll
            for (int it = 0; it < 2; it++) {
                int r = l_r + it * 16;
                As[r][l_kq * 4 + 0] = pa[it].x; As[r][l_kq * 4 + 1] = pa[it].y;
                As[r][l_kq * 4 + 2] = pa[it].z; As[r][l_kq * 4 + 3] = pa[it].w;
            }
#pragma unroll
            for (int it = 0; it < 4; it++) {
                int c = l_r + it * 16;
                Bs[l_kq * 4 + 0][c] = pb[it].x; Bs[l_kq * 4 + 1][c] = pb[it].y;
                Bs[l_kq * 4 + 2][c] = pb[it].z; Bs[l_kq * 4 + 3][c] = pb[it].w;
            }
            __syncthreads();
        }
    }

    // h2 tile -> smem with bias + ReLU
#pragma unroll
    for (int i = 0; i < 2; i++) {
        const int r = ty2 + i;
#pragma unroll
        for (int half = 0; half < 2; half++) {
            const int c = half * 32 + tx * 4;
            float2 p0 = upk2(acc[i][half * 2 + 0]);
            float2 p1 = upk2(acc[i][half * 2 + 1]);
            h2s[r][c + 0] = fmaxf(p0.x + b2s[c + 0], 0.0f);
            h2s[r][c + 1] = fmaxf(p0.y + b2s[c + 1], 0.0f);
            h2s[r][c + 2] = fmaxf(p1.x + b2s[c + 2], 0.0f);
            h2s[r][c + 3] = fmaxf(p1.y + b2s[c + 3], 0.0f);
        }
    }
    __syncthreads();

    // Projection: 64 work items (32 rows x 2 outs)
    if (tid < BM * O_DIM) {
        int r = tid >> 1, o = tid & 1;
        float s = 0.0f;
        const float* w = &wos[o * H2_DIM];
#pragma unroll
        for (int k = 0; k < H2_DIM; k++)
            s = fmaf(h2s[r][k], w[k], s);
        out[(size_t)(row0 + r) * O_DIM + o] = s + bos[o];
    }
}

// ---------------------------------------------------------------------------
extern "C" void kernel_launch(void* const* d_in, const int* in_sizes, int n_in,
                              void* d_out, int out_size)
{
    const float* x   = (const float*)d_in[0];
    const float* W1  = (const float*)d_in[1];
    const float* b1  = (const float*)d_in[2];
    const float* Wpr = (const float*)d_in[3];
    const float* bpr = (const float*)d_in[4];
    const float* W2  = (const float*)d_in[5];
    const float* b2  = (const float*)d_in[6];
    const float* Wo  = (const float*)d_in[7];
    const float* bo  = (const float*)d_in[8];
    float* out = (float*)d_out;

    float *part, *h1T, *pr0T, *pr1;
    cudaGetSymbolAddress((void**)&part, g_part);
    cudaGetSymbolAddress((void**)&h1T,  g_h1T);
    cudaGetSymbolAddress((void**)&pr0T, g_pr0T);
    cudaGetSymbolAddress((void**)&pr1,  g_pr1);

    // 1) gemm1 K-split: part[z] = x @ W1^T over K-chunk z  (1024 CTAs)
    gemm_split_kernel<<<dim3(B_DIM / 32, H1_DIM / 64, KSPLIT), 128>>>(
        x, W1, part, B_DIM, H1_DIM, KCHUNK, D_DIM);
    // 2) combine partials + b1 + relu, write transposed h1T [128][4096]
    combine_transpose_kernel<<<dim3(B_DIM / 32, H1_DIM / 32), 256>>>(
        part, b1, h1T);
    // 3) knn on transposed layout (coalesced load + store)
    knn_mean_kernel<<<H1_DIM, 1024>>>(h1T, pr0T);
    // 4) pr1 = relu(pr0 @ Wpr^T + bpr) via TN gemm on pr0T
    gemm_tn_kernel<<<dim3(B_DIM / 32, H1_DIM / 64), 128>>>(
        pr0T, Wpr, bpr, pr1, B_DIM, H1_DIM, H1_DIM);
    // 5) fused h2 + output projection
    tail_fused_kernel<<<B_DIM / 32, 128>>>(pr1, W2, b2, Wo, bo, out);
}

// round 13
// speedup vs baseline: 1.8671x; 1.0638x over previous
#include <cuda_runtime.h>
#include <cuda_bf16.h>
#include <cstdint>

#define B_DIM 4096
#define D_DIM 1024
#define H1_DIM 128
#define H2_DIM 64
#define O_DIM 2
#define KSPLIT 4
#define KCHUNK (D_DIM / KSPLIT)   // 256

// Scratch (no cudaMalloc allowed)
__device__ float g_part[KSPLIT * B_DIM * H1_DIM];  // gemm1 partials (8 MB)
__device__ float g_h1T[H1_DIM * B_DIM];            // h1 transposed [f][b]
__device__ float g_pr0T[H1_DIM * B_DIM];           // knn output transposed [f][b]

// ---------------------------------------------------------------------------
// Packed fp32x2 helpers (Blackwell FFMA2 — only reachable via PTX)
// ---------------------------------------------------------------------------
__device__ __forceinline__ unsigned long long pk2(float x, float y) {
    unsigned long long r;
    asm("mov.b64 %0, {%1, %2};" : "=l"(r) : "f"(x), "f"(y));
    return r;
}
__device__ __forceinline__ void ffma2(unsigned long long& d,
                                      unsigned long long a,
                                      unsigned long long b) {
    asm("fma.rn.f32x2 %0, %1, %2, %0;" : "+l"(d) : "l"(a), "l"(b));
}
__device__ __forceinline__ float2 upk2(unsigned long long v) {
    float2 f;
    asm("mov.b64 {%0, %1}, %2;" : "=f"(f.x), "=f"(f.y) : "l"(v));
    return f;
}

// ---------------------------------------------------------------------------
// Pipelined SGEMM with FFMA2 (NN): gemm1 K-split.
// BM=32, BN=64, BK=32, 128 threads. grid=(M/32, N/64, KSPLIT).
// Each z computes K-chunk [z*Kloop, (z+1)*Kloop) -> raw partial at C + z*M*N.
// ---------------------------------------------------------------------------
__global__ __launch_bounds__(128) void gemm_split_kernel(
    const float* __restrict__ A, const float* __restrict__ Bm,
    float* __restrict__ C, int M, int N, int Kloop, int lda)
{
    constexpr int BM = 32, BK = 32;
    __shared__ float As[BM][BK + 1];
    __shared__ float Bs[BK][68];

    const int tid = threadIdx.x;
    const int tx = tid & 7;
    const int ty = tid >> 3;
    const int row0 = blockIdx.x * BM;
    const int col0 = blockIdx.y * 64;
    const int z = blockIdx.z;

    const float* Ap = A + (size_t)z * Kloop;
    const float* Bp = Bm + (size_t)col0 * lda + (size_t)z * Kloop;
    float* Cz = C + (size_t)z * M * N;

    const int l_kq = tid & 7;
    const int l_r  = tid >> 3;

    unsigned long long acc[2][4];
#pragma unroll
    for (int i = 0; i < 2; i++)
#pragma unroll
        for (int j = 0; j < 4; j++) acc[i][j] = 0ull;

    const int NB = Kloop / BK;
    float4 pa[2], pb[4];

#pragma unroll
    for (int it = 0; it < 2; it++)
        pa[it] = *(const float4*)&Ap[(size_t)(row0 + l_r + it * 16) * lda + l_kq * 4];
#pragma unroll
    for (int it = 0; it < 4; it++)
        pb[it] = *(const float4*)&Bp[(size_t)(l_r + it * 16) * lda + l_kq * 4];

#pragma unroll
    for (int it = 0; it < 2; it++) {
        int r = l_r + it * 16;
        As[r][l_kq * 4 + 0] = pa[it].x; As[r][l_kq * 4 + 1] = pa[it].y;
        As[r][l_kq * 4 + 2] = pa[it].z; As[r][l_kq * 4 + 3] = pa[it].w;
    }
#pragma unroll
    for (int it = 0; it < 4; it++) {
        int f = l_r + it * 16;
        Bs[l_kq * 4 + 0][f] = pb[it].x; Bs[l_kq * 4 + 1][f] = pb[it].y;
        Bs[l_kq * 4 + 2][f] = pb[it].z; Bs[l_kq * 4 + 3][f] = pb[it].w;
    }
    __syncthreads();

    const int ty2 = ty * 2;
    for (int kb = 0; kb < NB; kb++) {
        const bool more = (kb + 1 < NB);
        if (more) {
            const int k0 = (kb + 1) * BK;
#pragma unroll
            for (int it = 0; it < 2; it++)
                pa[it] = *(const float4*)&Ap[(size_t)(row0 + l_r + it * 16) * lda + k0 + l_kq * 4];
#pragma unroll
            for (int it = 0; it < 4; it++)
                pb[it] = *(const float4*)&Bp[(size_t)(l_r + it * 16) * lda + k0 + l_kq * 4];
        }

#pragma unroll
        for (int kk = 0; kk < BK; kk++) {
            float a0 = As[ty2][kk];
            float a1 = As[ty2 + 1][kk];
            unsigned long long ap0 = pk2(a0, a0);
            unsigned long long ap1 = pk2(a1, a1);
            ulonglong2 b01 = *(const ulonglong2*)&Bs[kk][tx * 4];
            ulonglong2 b23 = *(const ulonglong2*)&Bs[kk][32 + tx * 4];
            ffma2(acc[0][0], ap0, b01.x); ffma2(acc[0][1], ap0, b01.y);
            ffma2(acc[0][2], ap0, b23.x); ffma2(acc[0][3], ap0, b23.y);
            ffma2(acc[1][0], ap1, b01.x); ffma2(acc[1][1], ap1, b01.y);
            ffma2(acc[1][2], ap1, b23.x); ffma2(acc[1][3], ap1, b23.y);
        }
        __syncthreads();
        if (more) {
#pragma unroll
            for (int it = 0; it < 2; it++) {
                int r = l_r + it * 16;
                As[r][l_kq * 4 + 0] = pa[it].x; As[r][l_kq * 4 + 1] = pa[it].y;
                As[r][l_kq * 4 + 2] = pa[it].z; As[r][l_kq * 4 + 3] = pa[it].w;
            }
#pragma unroll
            for (int it = 0; it < 4; it++) {
                int f = l_r + it * 16;
                Bs[l_kq * 4 + 0][f] = pb[it].x; Bs[l_kq * 4 + 1][f] = pb[it].y;
                Bs[l_kq * 4 + 2][f] = pb[it].z; Bs[l_kq * 4 + 3][f] = pb[it].w;
            }
            __syncthreads();
        }
    }

#pragma unroll
    for (int i = 0; i < 2; i++) {
        const int r = row0 + ty2 + i;
#pragma unroll
        for (int half = 0; half < 2; half++) {
            const int c = half * 32 + tx * 4;
            float2 p0 = upk2(acc[i][half * 2 + 0]);
            float2 p1 = upk2(acc[i][half * 2 + 1]);
            *(float4*)&Cz[(size_t)r * N + col0 + c] =
                make_float4(p0.x, p0.y, p1.x, p1.y);
        }
    }
}

// ---------------------------------------------------------------------------
// Combine K-split partials + bias + ReLU, writing h1 TRANSPOSED:
// h1T[f][b] = relu(sum_z part_z[b][f] + b1[f]). Coalesced both sides.
// ---------------------------------------------------------------------------
__global__ __launch_bounds__(256) void combine_transpose_kernel(
    const float* __restrict__ part, const float* __restrict__ b1,
    float* __restrict__ h1T)
{
    __shared__ float t[32][33];
    const int bx = blockIdx.x * 32;
    const int fx = blockIdx.y * 32;
    const int tid = threadIdx.x;
    const int x = tid & 7;
    const int y = tid >> 3;

    const size_t BH = (size_t)B_DIM * H1_DIM;
    const size_t idx = (size_t)(bx + y) * H1_DIM + fx + x * 4;
    float4 s  = *(const float4*)&part[idx];
    float4 p1 = *(const float4*)&part[idx + BH];
    float4 p2 = *(const float4*)&part[idx + 2 * BH];
    float4 p3 = *(const float4*)&part[idx + 3 * BH];
    s.x += p1.x; s.y += p1.y; s.z += p1.z; s.w += p1.w;
    s.x += p2.x; s.y += p2.y; s.z += p2.z; s.w += p2.w;
    s.x += p3.x; s.y += p3.y; s.z += p3.z; s.w += p3.w;
    const float4 bv = *(const float4*)&b1[fx + x * 4];
    t[y][x * 4 + 0] = fmaxf(s.x + bv.x, 0.0f);
    t[y][x * 4 + 1] = fmaxf(s.y + bv.y, 0.0f);
    t[y][x * 4 + 2] = fmaxf(s.z + bv.z, 0.0f);
    t[y][x * 4 + 3] = fmaxf(s.w + bv.w, 0.0f);
    __syncthreads();

    float4 o;
    o.x = t[x * 4 + 0][y];
    o.y = t[x * 4 + 1][y];
    o.z = t[x * 4 + 2][y];
    o.w = t[x * 4 + 3][y];
    *(float4*)&h1T[(size_t)(fx + y) * B_DIM + bx + x * 4] = o;
}

// ---------------------------------------------------------------------------
// Per-feature 6-NN batch averaging on TRANSPOSED layout (coalesced I/O).
// Hybrid bitonic sort (registers / shuffles / smem). Unchanged from r12.
// ---------------------------------------------------------------------------
__device__ __forceinline__ void ce_u32(unsigned int& a, unsigned int& b, bool up) {
    unsigned int mn = min(a, b), mx = max(a, b);
    a = up ? mn : mx;
    b = up ? mx : mn;
}

__global__ __launch_bounds__(1024) void knn_mean_kernel(
    const float* __restrict__ h1T, float* __restrict__ outT)
{
    __shared__ unsigned int sv[B_DIM];  // 16 KB

    const int f = blockIdx.x;
    const int t = threadIdx.x;
    const int lane = t & 31;
    const unsigned int i0 = 4u * (unsigned)t;

    unsigned int v[4], myv[4];
    {
        const uint4 hv = *(const uint4*)&h1T[(size_t)f * B_DIM + i0];
        v[0] = hv.x; v[1] = hv.y; v[2] = hv.z; v[3] = hv.w;
#pragma unroll
        for (int e = 0; e < 4; e++) myv[e] = v[e];
    }

    {
        if (v[0] > v[1]) { unsigned int tm = v[0]; v[0] = v[1]; v[1] = tm; }
        if (v[2] < v[3]) { unsigned int tm = v[2]; v[2] = v[3]; v[3] = tm; }
    }
    {
        bool up = (t & 1) == 0;
        ce_u32(v[0], v[2], up); ce_u32(v[1], v[3], up);
        ce_u32(v[0], v[1], up); ce_u32(v[2], v[3], up);
    }

    for (unsigned int k = 8; k <= B_DIM; k <<= 1) {
        const bool up = ((i0 & k) == 0);
        unsigned int j = k >> 1;

        if (j >= 128) {
            *(uint4*)&sv[i0] = make_uint4(v[0], v[1], v[2], v[3]);
            __syncthreads();
            for (; j >= 128; j >>= 1) {
#pragma unroll 2
                for (int p = t; p < B_DIM / 2; p += 1024) {
                    int i = ((p & ~(int)(j - 1)) << 1) | (p & (int)(j - 1));
                    int ixj = i | (int)j;
                    unsigned int a = sv[i];
                    unsigned int b = sv[ixj];
                    bool u2 = ((i & (int)k) == 0);
                    if (u2 ? (a > b) : (a < b)) { sv[i] = b; sv[ixj] = a; }
                }
                __syncthreads();
            }
            uint4 u = *(const uint4*)&sv[i0];
            v[0] = u.x; v[1] = u.y; v[2] = u.z; v[3] = u.w;
        }

        for (; j >= 4; j >>= 1) {
            const unsigned int d = j >> 2;
            const bool keepmin = (up == ((lane & d) == 0));
#pragma unroll
            for (int e = 0; e < 4; e++) {
                unsigned int o = __shfl_xor_sync(0xFFFFFFFFu, v[e], d);
                unsigned int mn = min(v[e], o), mx = max(v[e], o);
                v[e] = keepmin ? mn : mx;
            }
        }

        ce_u32(v[0], v[2], up); ce_u32(v[1], v[3], up);
        ce_u32(v[0], v[1], up); ce_u32(v[2], v[3], up);
    }

    *(uint4*)&sv[i0] = make_uint4(v[0], v[1], v[2], v[3]);
    __syncthreads();

    const float BIG = __int_as_float(0x7f000000);
    float res[4];

#pragma unroll
    for (int e = 0; e < 4; e++) {
        const unsigned int vb = myv[e];
        int lo = 0, hi = B_DIM;
#pragma unroll
        for (int s = 0; s < 12; s++) {
            int mid = (lo + hi) >> 1;
            if (sv[mid] < vb) lo = mid + 1; else hi = mid;
        }
        int p = lo;
        float val = __uint_as_float(vb);
        float sum = val;
        int l = p - 1, r = p + 1;
#pragma unroll
        for (int s = 0; s < 5; s++) {
            float vl = (l >= 0)     ? __uint_as_float(sv[l]) : 0.0f;
            float vr = (r < B_DIM)  ? __uint_as_float(sv[r]) : 0.0f;
            float dl = (l >= 0)     ? (val - vl) : BIG;
            float dr = (r < B_DIM)  ? (vr - val) : BIG;
            if (dl <= dr) { sum += vl; l--; }
            else          { sum += vr; r++; }
        }
        res[e] = sum * (1.0f / 6.0f);
    }

    *(float4*)&outT[(size_t)f * B_DIM + i0] =
        make_float4(res[0], res[1], res[2], res[3]);
}

// ---------------------------------------------------------------------------
// Fully fused PR tail:
//   pr1 = relu(pr0T^T @ Wpr^T + bpr)   (TN gemm, BM=32, BN=128 = all cols)
//   h2  = relu(pr1 @ W2^T + b2)        (in-CTA, chunked W2)
//   out = h2 @ Wo^T + bo
// 128 CTAs x 128 threads. Shared memory phase-aliased through one pool.
// ---------------------------------------------------------------------------
__global__ __launch_bounds__(128) void pr_tail_fused_kernel(
    const float* __restrict__ AT,    // pr0T [128][4096]
    const float* __restrict__ Wpr,   // [128][128] K-major
    const float* __restrict__ bpr,   // [128]
    const float* __restrict__ W2,    // [64][128]
    const float* __restrict__ b2,    // [64]
    const float* __restrict__ Wo,    // [2,64]
    const float* __restrict__ bo,    // [2]
    float* __restrict__ out)         // [4096,2]
{
    constexpr int BM = 32, BK = 32, K = H1_DIM, M = B_DIM, NB = K / BK;

    // Pool: phase1 As2[32][34] (4352 B) + Bs[32][132] (16896 B) = 21248 B
    //       phase2 prs[32][132] (16896) + w2c[32][68] (8704) + h2s[32][65] (8320) = 33920 B
    __shared__ __align__(16) char pool[33920];
    float (*As2)[34]  = (float(*)[34])pool;                  // [k][m]
    float (*Bs)[132]  = (float(*)[132])(pool + 4352);        // [k][n]
    float (*prs)[132] = (float(*)[132])pool;                 // pr1 tile [m][k]
    float (*w2c)[68]  = (float(*)[68])(pool + 16896);        // W2 chunk [k][c]
    float (*h2s)[65]  = (float(*)[65])(pool + 25600);        // h2 tile
    __shared__ float wos[O_DIM * H2_DIM];
    __shared__ float bprs[H1_DIM];
    __shared__ float b2s[H2_DIM];
    __shared__ float bos[O_DIM];

    const int tid = threadIdx.x;
    const int tx = tid & 7;
    const int ty = tid >> 3;
    const int row0 = blockIdx.x * BM;
    const int l_kq = tid & 7;
    const int l_r  = tid >> 3;

    wos[tid]  = Wo[tid];     // 128 elems
    bprs[tid] = bpr[tid];    // 128 elems
    if (tid < H2_DIM) b2s[tid] = b2[tid];
    if (tid < O_DIM)  bos[tid] = bo[tid];

    unsigned long long acc[2][8];
#pragma unroll
    for (int i = 0; i < 2; i++)
#pragma unroll
        for (int j = 0; j < 8; j++) acc[i][j] = 0ull;

    float4 pa[2], pb[8];
#pragma unroll
    for (int it = 0; it < 2; it++)
        pa[it] = *(const float4*)&AT[(size_t)(l_r + it * 16) * M + row0 + l_kq * 4];
#pragma unroll
    for (int it = 0; it < 8; it++)
        pb[it] = *(const float4*)&Wpr[(size_t)(l_r + it * 16) * K + l_kq * 4];

#pragma unroll
    for (int it = 0; it < 2; it++) {
        int kr = l_r + it * 16;
        As2[kr][l_kq * 4 + 0] = pa[it].x; As2[kr][l_kq * 4 + 1] = pa[it].y;
        As2[kr][l_kq * 4 + 2] = pa[it].z; As2[kr][l_kq * 4 + 3] = pa[it].w;
    }
#pragma unroll
    for (int it = 0; it < 8; it++) {
        int f = l_r + it * 16;
        Bs[l_kq * 4 + 0][f] = pb[it].x; Bs[l_kq * 4 + 1][f] = pb[it].y;
        Bs[l_kq * 4 + 2][f] = pb[it].z; Bs[l_kq * 4 + 3][f] = pb[it].w;
    }
    __syncthreads();

    const int ty2 = ty * 2;
    for (int kb = 0; kb < NB; kb++) {
        const bool more = (kb + 1 < NB);
        if (more) {
            const int k0 = (kb + 1) * BK;
#pragma unroll
            for (int it = 0; it < 2; it++)
                pa[it] = *(const float4*)&AT[(size_t)(k0 + l_r + it * 16) * M + row0 + l_kq * 4];
#pragma unroll
            for (int it = 0; it < 8; it++)
                pb[it] = *(const float4*)&Wpr[(size_t)(l_r + it * 16) * K + k0 + l_kq * 4];
        }

#pragma unroll
        for (int kk = 0; kk < BK; kk++) {
            float2 a = *(const float2*)&As2[kk][ty2];
            unsigned long long ap0 = pk2(a.x, a.x);
            unsigned long long ap1 = pk2(a.y, a.y);
#pragma unroll
            for (int q = 0; q < 4; q++) {
                ulonglong2 bq = *(const ulonglong2*)&Bs[kk][q * 32 + tx * 4];
                ffma2(acc[0][q * 2 + 0], ap0, bq.x);
                ffma2(acc[0][q * 2 + 1], ap0, bq.y);
                ffma2(acc[1][q * 2 + 0], ap1, bq.x);
                ffma2(acc[1][q * 2 + 1], ap1, bq.y);
            }
        }
        __syncthreads();
        if (more) {
#pragma unroll
            for (int it = 0; it < 2; it++) {
                int kr = l_r + it * 16;
                As2[kr][l_kq * 4 + 0] = pa[it].x; As2[kr][l_kq * 4 + 1] = pa[it].y;
                As2[kr][l_kq * 4 + 2] = pa[it].z; As2[kr][l_kq * 4 + 3] = pa[it].w;
            }
#pragma unroll
            for (int it = 0; it < 8; it++) {
                int f = l_r + it * 16;
                Bs[l_kq * 4 + 0][f] = pb[it].x; Bs[l_kq * 4 + 1][f] = pb[it].y;
                Bs[l_kq * 4 + 2][f] = pb[it].z; Bs[l_kq * 4 + 3][f] = pb[it].w;
            }
            __syncthreads();
        }
    }
    // (last mainloop iteration ended with __syncthreads: As2/Bs now dead)

    // pr1 tile -> prs (aliases pool) with bias + ReLU
#pragma unroll
    for (int i = 0; i < 2; i++) {
        const int r = ty2 + i;
#pragma unroll
        for (int q = 0; q < 4; q++) {
            const int c = q * 32 + tx * 4;
            float2 p0 = upk2(acc[i][q * 2 + 0]);
            float2 p1 = upk2(acc[i][q * 2 + 1]);
            prs[r][c + 0] = fmaxf(p0.x + bprs[c + 0], 0.0f);
            prs[r][c + 1] = fmaxf(p0.y + bprs[c + 1], 0.0f);
            prs[r][c + 2] = fmaxf(p1.x + bprs[c + 2], 0.0f);
            prs[r][c + 3] = fmaxf(p1.y + bprs[c + 3], 0.0f);
        }
    }
    __syncthreads();

    // h2 = relu(prs @ W2^T + b2), W2 consumed in 4 chunks of 32 k
    const int tx2 = tid & 15;   // cols tx2*4 .. +3
    const int tyB = tid >> 4;   // rows tyB*4 .. +3
    float acc2[4][4];
#pragma unroll
    for (int i = 0; i < 4; i++)
#pragma unroll
        for (int j = 0; j < 4; j++) acc2[i][j] = 0.0f;

    for (int kb2 = 0; kb2 < 4; kb2++) {
        // load W2 chunk [64 c][32 k] transposed into w2c[k][c]
#pragma unroll
        for (int it = 0; it < 4; it++) {
            int c = l_r + it * 16;
            float4 w = *(const float4*)&W2[(size_t)c * K + kb2 * 32 + l_kq * 4];
            w2c[l_kq * 4 + 0][c] = w.x;
            w2c[l_kq * 4 + 1][c] = w.y;
            w2c[l_kq * 4 + 2][c] = w.z;
            w2c[l_kq * 4 + 3][c] = w.w;
        }
        __syncthreads();
#pragma unroll
        for (int kk = 0; kk < 32; kk++) {
            float4 wv = *(const float4*)&w2c[kk][tx2 * 4];
            float p0 = prs[tyB * 4 + 0][kb2 * 32 + kk];
            float p1 = prs[tyB * 4 + 1][kb2 * 32 + kk];
            float p2 = prs[tyB * 4 + 2][kb2 * 32 + kk];
            float p3 = prs[tyB * 4 + 3][kb2 * 32 + kk];
            acc2[0][0] = fmaf(p0, wv.x, acc2[0][0]); acc2[0][1] = fmaf(p0, wv.y, acc2[0][1]);
            acc2[0][2] = fmaf(p0, wv.z, acc2[0][2]); acc2[0][3] = fmaf(p0, wv.w, acc2[0][3]);
            acc2[1][0] = fmaf(p1, wv.x, acc2[1][0]); acc2[1][1] = fmaf(p1, wv.y, acc2[1][1]);
            acc2[1][2] = fmaf(p1, wv.z, acc2[1][2]); acc2[1][3] = fmaf(p1, wv.w, acc2[1][3]);
            acc2[2][0] = fmaf(p2, wv.x, acc2[2][0]); acc2[2][1] = fmaf(p2, wv.y, acc2[2][1]);
            acc2[2][2] = fmaf(p2, wv.z, acc2[2][2]); acc2[2][3] = fmaf(p2, wv.w, acc2[2][3]);
            acc2[3][0] = fmaf(p3, wv.x, acc2[3][0]); acc2[3][1] = fmaf(p3, wv.y, acc2[3][1]);
            acc2[3][2] = fmaf(p3, wv.z, acc2[3][2]); acc2[3][3] = fmaf(p3, wv.w, acc2[3][3]);
        }
        __syncthreads();
    }

    // h2s with bias + ReLU
#pragma unroll
    for (int i = 0; i < 4; i++)
#pragma unroll
        for (int j = 0; j < 4; j++) {
            int c = tx2 * 4 + j;
            h2s[tyB * 4 + i][c] = fmaxf(acc2[i][j] + b2s[c], 0.0f);
        }
    __syncthreads();

    // Projection: 64 work items (32 rows x 2 outs)
    if (tid < BM * O_DIM) {
        int r = tid >> 1, o = tid & 1;
        float s = 0.0f;
        const float* w = &wos[o * H2_DIM];
#pragma unroll
        for (int k = 0; k < H2_DIM; k++)
            s = fmaf(h2s[r][k], w[k], s);
        out[(size_t)(row0 + r) * O_DIM + o] = s + bos[o];
    }
}

// ---------------------------------------------------------------------------
extern "C" void kernel_launch(void* const* d_in, const int* in_sizes, int n_in,
                              void* d_out, int out_size)
{
    const float* x   = (const float*)d_in[0];
    const float* W1  = (const float*)d_in[1];
    const float* b1  = (const float*)d_in[2];
    const float* Wpr = (const float*)d_in[3];
    const float* bpr = (const float*)d_in[4];
    const float* W2  = (const float*)d_in[5];
    const float* b2  = (const float*)d_in[6];
    const float* Wo  = (const float*)d_in[7];
    const float* bo  = (const float*)d_in[8];
    float* out = (float*)d_out;

    float *part, *h1T, *pr0T;
    cudaGetSymbolAddress((void**)&part, g_part);
    cudaGetSymbolAddress((void**)&h1T,  g_h1T);
    cudaGetSymbolAddress((void**)&pr0T, g_pr0T);

    // 1) gemm1 K-split: part[z] = x @ W1^T over K-chunk z  (1024 CTAs)
    gemm_split_kernel<<<dim3(B_DIM / 32, H1_DIM / 64, KSPLIT), 128>>>(
        x, W1, part, B_DIM, H1_DIM, KCHUNK, D_DIM);
    // 2) combine partials + b1 + relu, write transposed h1T [128][4096]
    combine_transpose_kernel<<<dim3(B_DIM / 32, H1_DIM / 32), 256>>>(
        part, b1, h1T);
    // 3) knn on transposed layout (coalesced load + store)
    knn_mean_kernel<<<H1_DIM, 1024>>>(h1T, pr0T);
    // 4) fused pr1 + h2 + output projection (one kernel, no pr1 round-trip)
    pr_tail_fused_kernel<<<B_DIM / 32, 128>>>(
        pr0T, Wpr, bpr, W2, b2, Wo, bo, out);
}